// round 2
// baseline (speedup 1.0000x reference)
#include <cuda_runtime.h>
#include <math.h>

// Problem constants: B=32, LI=LJ=D=H(=2*NN_DIM)=512
#define LD 512
#define NBATCH 32

// Scratch (device globals: no allocations allowed in kernel_launch)
__device__ float g_S [(long long)NBATCH*LD*LD]; // scores [b][i][j]
__device__ float g_wj[(long long)NBATCH*LD*LD]; // weighted_j [b][i][d]
__device__ float g_wi[(long long)NBATCH*LD*LD]; // weighted_i [b][j][d]
__device__ float g_rmax[NBATCH*LD];
__device__ float g_rz  [NBATCH*LD];   // 1/sum_exp over j (row softmax)
__device__ float g_cmax[NBATCH*LD];
__device__ float g_cz  [NBATCH*LD];   // 1/sum_exp over i (col softmax)
__device__ float g_oi[NBATCH*LD];     // column sums of tanh(.) for output_i
__device__ float g_oj[NBATCH*LD];

// ---------------------------------------------------------------------------
// Kernel 1: S[b] = i[b] @ j[b]^T   (NT GEMM, 512x512x512 per batch)
// Tiles: BM=BN=64, BK=16, 256 threads, 4x4 micro-tile per thread.
// ---------------------------------------------------------------------------
__global__ __launch_bounds__(256) void k_scores(const float* __restrict__ I,
                                                const float* __restrict__ J)
{
    __shared__ __align__(16) float As[16][68];
    __shared__ __align__(16) float Bs[16][68];
    const int b  = blockIdx.z;
    const int m0 = blockIdx.y * 64, n0 = blockIdx.x * 64;
    const float* A  = I + (long long)b * LD * LD;
    const float* Bg = J + (long long)b * LD * LD;
    float*       C  = g_S + (long long)b * LD * LD;
    const int tid = threadIdx.x;
    const int tx = tid & 15, ty = tid >> 4;
    const int lr = tid >> 2, lc = (tid & 3) << 2;   // 64 rows x 16 k, float4
    float acc[4][4] = {};
    for (int kk = 0; kk < LD; kk += 16) {
        float4 av = *(const float4*)&A [(m0 + lr) * LD + kk + lc];
        float4 bv = *(const float4*)&Bg[(n0 + lr) * LD + kk + lc];
        As[lc+0][lr]=av.x; As[lc+1][lr]=av.y; As[lc+2][lr]=av.z; As[lc+3][lr]=av.w;
        Bs[lc+0][lr]=bv.x; Bs[lc+1][lr]=bv.y; Bs[lc+2][lr]=bv.z; Bs[lc+3][lr]=bv.w;
        __syncthreads();
        #pragma unroll
        for (int k = 0; k < 16; ++k) {
            float4 a  = *(const float4*)&As[k][ty << 2];
            float4 bb = *(const float4*)&Bs[k][tx << 2];
            float ar[4] = {a.x, a.y, a.z, a.w};
            float br[4] = {bb.x, bb.y, bb.z, bb.w};
            #pragma unroll
            for (int u = 0; u < 4; ++u)
                #pragma unroll
                for (int v = 0; v < 4; ++v) acc[u][v] += ar[u] * br[v];
        }
        __syncthreads();
    }
    #pragma unroll
    for (int u = 0; u < 4; ++u) {
        float4 o = make_float4(acc[u][0], acc[u][1], acc[u][2], acc[u][3]);
        *(float4*)&C[(m0 + (ty << 2) + u) * LD + n0 + (tx << 2)] = o;
    }
}

// ---------------------------------------------------------------------------
// Kernel 2a: row softmax stats (over j). One warp per row.
// ---------------------------------------------------------------------------
__global__ __launch_bounds__(256) void k_rowstats()
{
    const int row  = blockIdx.x * 8 + (threadIdx.x >> 5); // global row in [0, NB*LD)
    const int lane = threadIdx.x & 31;
    const float* s = g_S + (long long)row * LD;
    float mx = -1e30f;
    for (int t = lane; t < LD; t += 32) mx = fmaxf(mx, s[t]);
    #pragma unroll
    for (int o = 16; o; o >>= 1) mx = fmaxf(mx, __shfl_xor_sync(0xffffffffu, mx, o));
    float sum = 0.f;
    for (int t = lane; t < LD; t += 32) sum += __expf(s[t] - mx);
    #pragma unroll
    for (int o = 16; o; o >>= 1) sum += __shfl_xor_sync(0xffffffffu, sum, o);
    if (lane == 0) { g_rmax[row] = mx; g_rz[row] = 1.0f / sum; }
}

// ---------------------------------------------------------------------------
// Kernel 2b: column softmax stats (over i). Thread per column, coalesced.
// ---------------------------------------------------------------------------
__global__ __launch_bounds__(256) void k_colstats()
{
    const int b = blockIdx.y;
    const int j = blockIdx.x * 256 + threadIdx.x;
    const float* s = g_S + (long long)b * LD * LD + j;
    float mx = -1e30f;
    for (int i2 = 0; i2 < LD; ++i2) mx = fmaxf(mx, s[i2 * LD]);
    float sum = 0.f;
    for (int i2 = 0; i2 < LD; ++i2) sum += __expf(s[i2 * LD] - mx);
    g_cmax[b * LD + j] = mx;
    g_cz  [b * LD + j] = 1.0f / sum;
}

// ---------------------------------------------------------------------------
// Kernel 3a: weighted_j[b] = softmax_row(S[b]) @ j[b]
// A[m][k] = exp(S[m][k]-rmax[m])*rz[m]  (m=i, k=j), B[k][n] = j[k][n]
// ---------------------------------------------------------------------------
__global__ __launch_bounds__(256) void k_wj(const float* __restrict__ J)
{
    __shared__ __align__(16) float As[16][68];
    __shared__ __align__(16) float Bs[16][68];
    const int b  = blockIdx.z;
    const int m0 = blockIdx.y * 64, n0 = blockIdx.x * 64;
    const float* S  = g_S + (long long)b * LD * LD;
    const float* Bg = J   + (long long)b * LD * LD;
    float*       C  = g_wj + (long long)b * LD * LD;
    const int tid = threadIdx.x;
    const int tx = tid & 15, ty = tid >> 4;
    const int lr = tid >> 2, lc = (tid & 3) << 2;
    const int kr = tid >> 4, nc = (tid & 15) << 2;
    const float rm = g_rmax[b * LD + m0 + lr];
    const float rz = g_rz  [b * LD + m0 + lr];
    float acc[4][4] = {};
    for (int kk = 0; kk < LD; kk += 16) {
        float4 av = *(const float4*)&S[(m0 + lr) * LD + kk + lc];
        As[lc+0][lr] = __expf(av.x - rm) * rz;
        As[lc+1][lr] = __expf(av.y - rm) * rz;
        As[lc+2][lr] = __expf(av.z - rm) * rz;
        As[lc+3][lr] = __expf(av.w - rm) * rz;
        *(float4*)&Bs[kr][nc] = *(const float4*)&Bg[(kk + kr) * LD + n0 + nc];
        __syncthreads();
        #pragma unroll
        for (int k = 0; k < 16; ++k) {
            float4 a  = *(const float4*)&As[k][ty << 2];
            float4 bb = *(const float4*)&Bs[k][tx << 2];
            float ar[4] = {a.x, a.y, a.z, a.w};
            float br[4] = {bb.x, bb.y, bb.z, bb.w};
            #pragma unroll
            for (int u = 0; u < 4; ++u)
                #pragma unroll
                for (int v = 0; v < 4; ++v) acc[u][v] += ar[u] * br[v];
        }
        __syncthreads();
    }
    #pragma unroll
    for (int u = 0; u < 4; ++u) {
        float4 o = make_float4(acc[u][0], acc[u][1], acc[u][2], acc[u][3]);
        *(float4*)&C[(m0 + (ty << 2) + u) * LD + n0 + (tx << 2)] = o;
    }
}

// ---------------------------------------------------------------------------
// Kernel 3b: weighted_i[b] = softmax_col(S[b])^T @ i[b]
// m=j, k=i, n=d.  A'[m][k] = exp(S[k][m]-cmax[m])*cz[m] -> As[k][m] direct layout.
// ---------------------------------------------------------------------------
__global__ __launch_bounds__(256) void k_wi(const float* __restrict__ I)
{
    __shared__ __align__(16) float As[16][68];
    __shared__ __align__(16) float Bs[16][68];
    const int b  = blockIdx.z;
    const int m0 = blockIdx.y * 64, n0 = blockIdx.x * 64;
    const float* S  = g_S + (long long)b * LD * LD;
    const float* Bg = I   + (long long)b * LD * LD;
    float*       C  = g_wi + (long long)b * LD * LD;
    const int tid = threadIdx.x;
    const int tx = tid & 15, ty = tid >> 4;
    const int kr = tid >> 4, cc = (tid & 15) << 2;  // used for both A and B loads
    const float4 cm4 = *(const float4*)&g_cmax[b * LD + m0 + cc];
    const float4 cz4 = *(const float4*)&g_cz  [b * LD + m0 + cc];
    float acc[4][4] = {};
    for (int kk = 0; kk < LD; kk += 16) {
        float4 sv = *(const float4*)&S[(kk + kr) * LD + m0 + cc];
        As[kr][cc+0] = __expf(sv.x - cm4.x) * cz4.x;
        As[kr][cc+1] = __expf(sv.y - cm4.y) * cz4.y;
        As[kr][cc+2] = __expf(sv.z - cm4.z) * cz4.z;
        As[kr][cc+3] = __expf(sv.w - cm4.w) * cz4.w;
        *(float4*)&Bs[kr][cc] = *(const float4*)&Bg[(kk + kr) * LD + n0 + cc];
        __syncthreads();
        #pragma unroll
        for (int k = 0; k < 16; ++k) {
            float4 a  = *(const float4*)&As[k][ty << 2];
            float4 bb = *(const float4*)&Bs[k][tx << 2];
            float ar[4] = {a.x, a.y, a.z, a.w};
            float br[4] = {bb.x, bb.y, bb.z, bb.w};
            #pragma unroll
            for (int u = 0; u < 4; ++u)
                #pragma unroll
                for (int v = 0; v < 4; ++v) acc[u][v] += ar[u] * br[v];
        }
        __syncthreads();
    }
    #pragma unroll
    for (int u = 0; u < 4; ++u) {
        float4 o = make_float4(acc[u][0], acc[u][1], acc[u][2], acc[u][3]);
        *(float4*)&C[(m0 + (ty << 2) + u) * LD + n0 + (tx << 2)] = o;
    }
}

// ---------------------------------------------------------------------------
// Kernel 4: fused |x - w| @ W_agg + bias -> tanh -> column sum over all 512 rows.
// which=0: x=i, w=weighted_j -> g_oi ; which=1: x=j, w=weighted_i -> g_oj.
// Each block owns 64 output columns for one (batch, which): no atomics needed.
// ---------------------------------------------------------------------------
__global__ __launch_bounds__(256) void k_agg(const float* __restrict__ I,
                                             const float* __restrict__ J,
                                             const float* __restrict__ W,
                                             const float* __restrict__ bias)
{
    __shared__ __align__(16) float As[16][68];
    __shared__ __align__(16) float Bs[16][68];
    __shared__ float red[16][64];
    const int b     = blockIdx.y;
    const int which = blockIdx.z;
    const int n0    = blockIdx.x * 64;
    const float* P1 = (which == 0 ? I : J)       + (long long)b * LD * LD;
    const float* P2 = (which == 0 ? g_wj : g_wi) + (long long)b * LD * LD;
    float* Og       = (which == 0 ? g_oi : g_oj) + b * LD;
    const int tid = threadIdx.x;
    const int tx = tid & 15, ty = tid >> 4;
    const int lr = tid >> 2, lc = (tid & 3) << 2;
    const int kr = tid >> 4, nc = (tid & 15) << 2;
    float bia[4];
    #pragma unroll
    for (int v = 0; v < 4; ++v) bia[v] = bias[n0 + (tx << 2) + v];
    float csum[4] = {};
    for (int mb = 0; mb < LD; mb += 64) {
        float acc[4][4] = {};
        for (int kk = 0; kk < LD; kk += 16) {
            float4 x1 = *(const float4*)&P1[(mb + lr) * LD + kk + lc];
            float4 x2 = *(const float4*)&P2[(mb + lr) * LD + kk + lc];
            As[lc+0][lr] = fabsf(x1.x - x2.x);
            As[lc+1][lr] = fabsf(x1.y - x2.y);
            As[lc+2][lr] = fabsf(x1.z - x2.z);
            As[lc+3][lr] = fabsf(x1.w - x2.w);
            *(float4*)&Bs[kr][nc] = *(const float4*)&W[(kk + kr) * LD + n0 + nc];
            __syncthreads();
            #pragma unroll
            for (int k = 0; k < 16; ++k) {
                float4 a  = *(const float4*)&As[k][ty << 2];
                float4 bb = *(const float4*)&Bs[k][tx << 2];
                float ar[4] = {a.x, a.y, a.z, a.w};
                float br[4] = {bb.x, bb.y, bb.z, bb.w};
                #pragma unroll
                for (int u = 0; u < 4; ++u)
                    #pragma unroll
                    for (int v = 0; v < 4; ++v) acc[u][v] += ar[u] * br[v];
            }
            __syncthreads();
        }
        #pragma unroll
        for (int u = 0; u < 4; ++u)
            #pragma unroll
            for (int v = 0; v < 4; ++v) csum[v] += tanhf(acc[u][v] + bia[v]);
    }
    #pragma unroll
    for (int v = 0; v < 4; ++v) red[ty][(tx << 2) + v] = csum[v];
    __syncthreads();
    if (tid < 64) {
        float s = 0.f;
        #pragma unroll
        for (int t = 0; t < 16; ++t) s += red[t][tid];
        Og[n0 + tid] = s;   // column SUM (mean scaling applied in combine)
    }
}

// ---------------------------------------------------------------------------
// Kernel 5: out = 0.5 * (oi_sum/512 + oj_sum/512)
// ---------------------------------------------------------------------------
__global__ void k_combine(float* __restrict__ out)
{
    const int idx = blockIdx.x * 256 + threadIdx.x;
    out[idx] = (g_oi[idx] + g_oj[idx]) * (0.5f / 512.0f);
}

// ---------------------------------------------------------------------------
extern "C" void kernel_launch(void* const* d_in, const int* in_sizes, int n_in,
                              void* d_out, int out_size)
{
    (void)in_sizes; (void)n_in; (void)out_size;
    const float* I    = (const float*)d_in[0];
    const float* J    = (const float*)d_in[1];
    const float* W    = (const float*)d_in[2];
    const float* bias = (const float*)d_in[3];
    float* out = (float*)d_out;

    dim3 gemm_grid(8, 8, NBATCH);
    k_scores  <<<gemm_grid, 256>>>(I, J);
    k_rowstats<<<NBATCH * LD / 8, 256>>>();
    k_colstats<<<dim3(2, NBATCH), 256>>>();
    k_wj      <<<gemm_grid, 256>>>(J);
    k_wi      <<<gemm_grid, 256>>>(I);
    k_agg     <<<dim3(8, NBATCH, 2), 256>>>(I, J, W, bias);
    k_combine <<<64, 256>>>(out);
}

// round 3
// speedup vs baseline: 2.0446x; 2.0446x over previous
#include <cuda_runtime.h>
#include <math.h>

#define LD 512
#define NB 32

// ------------------------- scratch (device globals) -------------------------
__device__ float g_S [(size_t)NB*LD*LD]; // scores [b][i][j]
__device__ float g_wj[(size_t)NB*LD*LD]; // weighted_j [b][i][d]
__device__ float g_wi[(size_t)NB*LD*LD]; // weighted_i [b][j][d]
__device__ float g_rmax[NB*LD], g_rz[NB*LD];
__device__ float g_cmax[NB*LD], g_cz[NB*LD];
__device__ float g_oi[NB*LD], g_oj[NB*LD];

// ------------------------- tf32 mma helpers ---------------------------------
__device__ __forceinline__ unsigned f2tf(float x){
    unsigned r; asm("cvt.rna.tf32.f32 %0, %1;" : "=r"(r) : "f"(x)); return r;
}
__device__ __forceinline__ uint4 tf_hi4(float4 v){
    uint4 o; o.x=f2tf(v.x); o.y=f2tf(v.y); o.z=f2tf(v.z); o.w=f2tf(v.w); return o;
}
__device__ __forceinline__ uint4 tf_lo4(float4 v, uint4 h){
    uint4 o;
    o.x=f2tf(v.x-__uint_as_float(h.x));
    o.y=f2tf(v.y-__uint_as_float(h.y));
    o.z=f2tf(v.z-__uint_as_float(h.z));
    o.w=f2tf(v.w-__uint_as_float(h.w));
    return o;
}
__device__ __forceinline__ void mma8(float* c, unsigned a0,unsigned a1,unsigned a2,unsigned a3,
                                     unsigned b0,unsigned b1){
    asm volatile("mma.sync.aligned.m16n8k8.row.col.f32.tf32.tf32.f32 "
        "{%0,%1,%2,%3}, {%4,%5,%6,%7}, {%8,%9}, {%0,%1,%2,%3};"
        : "+f"(c[0]),"+f"(c[1]),"+f"(c[2]),"+f"(c[3])
        : "r"(a0),"r"(a1),"r"(a2),"r"(a3),"r"(b0),"r"(b1));
}
__device__ __forceinline__ void ldmx4(unsigned* r, unsigned addr){
    asm volatile("ldmatrix.sync.aligned.m8n8.x4.shared.b16 {%0,%1,%2,%3}, [%4];"
        : "=r"(r[0]),"=r"(r[1]),"=r"(r[2]),"=r"(r[3]) : "r"(addr));
}
// A fragment (m16k8) ldmatrix.x4 address for this lane. RS = smem row stride (floats).
template<int RS>
__device__ __forceinline__ unsigned a_addr(unsigned base, int row0, int ks, int lane){
    int sub = lane>>3;
    int row = row0 + (lane&7) + ((sub&1)<<3);
    int kg  = (ks<<1) + (sub>>1);
    int g   = kg ^ ((row>>3)&3);
    return base + (unsigned)((row*RS + (g<<2))<<2);
}
// B fragments for two adjacent n8 tiles (n0, n0+8) in one ldmatrix.x4.
template<int RS>
__device__ __forceinline__ unsigned b_addr(unsigned base, int n0, int ks, int lane){
    int sub = lane>>3;
    int n   = n0 + (lane&7) + ((sub>>1)<<3);
    int kg  = (ks<<1) + (sub&1);
    int g   = kg ^ ((n>>3)&3);
    return base + (unsigned)((n*RS + (g<<2))<<2);
}

// one BK=32 chunk of warp-level mma (single tf32), stride 36
__device__ __forceinline__ void compute_chunk36(float c[4][4][4], unsigned uA, unsigned uB,
                                                int wm0, int wn0, int lane){
    #pragma unroll
    for (int ks = 0; ks < 4; ks++){
        unsigned bf[2][4];
        ldmx4(bf[0], b_addr<36>(uB, wn0,    ks, lane));
        ldmx4(bf[1], b_addr<36>(uB, wn0+16, ks, lane));
        #pragma unroll
        for (int mt = 0; mt < 4; mt++){
            unsigned af[4];
            ldmx4(af, a_addr<36>(uA, wm0+(mt<<4), ks, lane));
            #pragma unroll
            for (int nt = 0; nt < 4; nt++)
                mma8(c[mt][nt], af[0],af[1],af[2],af[3],
                     bf[nt>>1][(nt&1)<<1], bf[nt>>1][((nt&1)<<1)+1]);
        }
    }
}

// transpose-stage: read gB[k][n] (k=0..31 rows, n=0..127 cols, row stride LD),
// write sB[n][k] tf32-converted, swizzled, stride 36.
__device__ __forceinline__ void stage_T(float* sB, const float* gB, int tid){
    int l = tid&31, kb = tid>>5;
    int n = l<<2;
    int sw = (n>>3)&3;
    #pragma unroll
    for (int ki = 0; ki < 4; ki++){
        int k = kb + (ki<<3);
        float4 v = *(const float4*)&gB[(size_t)k*LD + n];
        int g = (k>>2) ^ sw;
        float* p = sB + n*36 + (g<<2) + (k&3);
        p[0]   = __uint_as_float(f2tf(v.x));
        p[36]  = __uint_as_float(f2tf(v.y));
        p[72]  = __uint_as_float(f2tf(v.z));
        p[108] = __uint_as_float(f2tf(v.w));
    }
}

// ---------------------------------------------------------------------------
// Kernel 1: S = I @ J^T  with 3xTF32 (hi/lo split) for fp32-grade accuracy.
// BM=BN=128, BK=16 (stride 20), 256 thr, 8 warps of 64x32.
// ---------------------------------------------------------------------------
__global__ __launch_bounds__(256,2) void k_scores(const float* __restrict__ I,
                                                  const float* __restrict__ J)
{
    __shared__ float sAh[128*20], sAl[128*20], sBh[128*20], sBl[128*20];
    const int b  = blockIdx.z;
    const int m0 = blockIdx.y*128, n0 = blockIdx.x*128;
    const float* A = I + (size_t)b*LD*LD;
    const float* B = J + (size_t)b*LD*LD;
    float*       C = g_S + (size_t)b*LD*LD;
    const int tid = threadIdx.x, lane = tid&31, warp = tid>>5;
    const int wm0 = (warp&1)<<6, wn0 = (warp>>1)<<5;
    unsigned uAh = (unsigned)__cvta_generic_to_shared(sAh);
    unsigned uAl = (unsigned)__cvta_generic_to_shared(sAl);
    unsigned uBh = (unsigned)__cvta_generic_to_shared(sBh);
    unsigned uBl = (unsigned)__cvta_generic_to_shared(sBl);
    const int sr = tid>>2, scg = tid&3;
    float c[4][4][4] = {};
    for (int kk = 0; kk < LD; kk += 16){
        #pragma unroll
        for (int rr = 0; rr < 2; rr++){
            int r = sr + (rr<<6);
            int off = r*20 + (((scg) ^ ((r>>3)&3))<<2);
            float4 va = *(const float4*)&A[(size_t)(m0+r)*LD + kk + (scg<<2)];
            float4 vb = *(const float4*)&B[(size_t)(n0+r)*LD + kk + (scg<<2)];
            uint4 Ha = tf_hi4(va), La = tf_lo4(va, Ha);
            uint4 Hb = tf_hi4(vb), Lb = tf_lo4(vb, Hb);
            *(uint4*)&sAh[off] = Ha; *(uint4*)&sAl[off] = La;
            *(uint4*)&sBh[off] = Hb; *(uint4*)&sBl[off] = Lb;
        }
        __syncthreads();
        #pragma unroll
        for (int ks = 0; ks < 2; ks++){
            unsigned bh[2][4], bl[2][4];
            ldmx4(bh[0], b_addr<20>(uBh, wn0,    ks, lane));
            ldmx4(bh[1], b_addr<20>(uBh, wn0+16, ks, lane));
            ldmx4(bl[0], b_addr<20>(uBl, wn0,    ks, lane));
            ldmx4(bl[1], b_addr<20>(uBl, wn0+16, ks, lane));
            #pragma unroll
            for (int mt = 0; mt < 4; mt++){
                unsigned ah[4], al[4];
                ldmx4(ah, a_addr<20>(uAh, wm0+(mt<<4), ks, lane));
                ldmx4(al, a_addr<20>(uAl, wm0+(mt<<4), ks, lane));
                #pragma unroll
                for (int nt = 0; nt < 4; nt++){
                    unsigned b0h = bh[nt>>1][(nt&1)<<1], b1h = bh[nt>>1][((nt&1)<<1)+1];
                    unsigned b0l = bl[nt>>1][(nt&1)<<1], b1l = bl[nt>>1][((nt&1)<<1)+1];
                    mma8(c[mt][nt], ah[0],ah[1],ah[2],ah[3], b0h, b1h); // hi*hi
                    mma8(c[mt][nt], ah[0],ah[1],ah[2],ah[3], b0l, b1l); // hi*lo
                    mma8(c[mt][nt], al[0],al[1],al[2],al[3], b0h, b1h); // lo*hi
                }
            }
        }
        __syncthreads();
    }
    #pragma unroll
    for (int mt = 0; mt < 4; mt++){
        int row = m0 + wm0 + (mt<<4) + (lane>>2);
        #pragma unroll
        for (int nt = 0; nt < 4; nt++){
            int col = n0 + wn0 + (nt<<3) + ((lane&3)<<1);
            *(float2*)&C[(size_t)row*LD + col]     = make_float2(c[mt][nt][0], c[mt][nt][1]);
            *(float2*)&C[(size_t)(row+8)*LD + col] = make_float2(c[mt][nt][2], c[mt][nt][3]);
        }
    }
}

// ---------------------------------------------------------------------------
// Kernel 2a/2b: softmax stats (unchanged math from R1)
// ---------------------------------------------------------------------------
__global__ __launch_bounds__(256) void k_rowstats()
{
    const int row  = blockIdx.x * 8 + (threadIdx.x >> 5);
    const int lane = threadIdx.x & 31;
    const float* s = g_S + (size_t)row * LD;
    float mx = -1e30f;
    for (int t = lane; t < LD; t += 32) mx = fmaxf(mx, s[t]);
    #pragma unroll
    for (int o = 16; o; o >>= 1) mx = fmaxf(mx, __shfl_xor_sync(0xffffffffu, mx, o));
    float sum = 0.f;
    for (int t = lane; t < LD; t += 32) sum += __expf(s[t] - mx);
    #pragma unroll
    for (int o = 16; o; o >>= 1) sum += __shfl_xor_sync(0xffffffffu, sum, o);
    if (lane == 0) { g_rmax[row] = mx; g_rz[row] = 1.0f / sum; }
}

__global__ __launch_bounds__(128) void k_colstats()
{
    const int b = blockIdx.y;
    const int j = blockIdx.x * 128 + threadIdx.x;
    const float* s = g_S + (size_t)b * LD * LD + j;
    float mx = -1e30f;
    #pragma unroll 4
    for (int i2 = 0; i2 < LD; ++i2) mx = fmaxf(mx, s[(size_t)i2 * LD]);
    float sum = 0.f;
    #pragma unroll 4
    for (int i2 = 0; i2 < LD; ++i2) sum += __expf(s[(size_t)i2 * LD] - mx);
    g_cmax[b * LD + j] = mx;
    g_cz  [b * LD + j] = 1.0f / sum;
}

// ---------------------------------------------------------------------------
// Kernel 3a: weighted_j = softmax_row(S) @ J   (A: exp-staged row-major; B: J^T staged)
// ---------------------------------------------------------------------------
__global__ __launch_bounds__(256,2) void k_wj(const float* __restrict__ Jg)
{
    __shared__ float sA[128*36], sB[128*36];
    const int b  = blockIdx.z;
    const int m0 = blockIdx.y*128, n0 = blockIdx.x*128;
    const float* S  = g_S + (size_t)b*LD*LD;
    const float* Bg = Jg  + (size_t)b*LD*LD;
    float*       C  = g_wj + (size_t)b*LD*LD;
    const int tid = threadIdx.x, lane = tid&31, warp = tid>>5;
    const int wm0 = (warp&1)<<6, wn0 = (warp>>1)<<5;
    unsigned uA = (unsigned)__cvta_generic_to_shared(sA);
    unsigned uB = (unsigned)__cvta_generic_to_shared(sB);
    const int sr = tid>>3, cg = tid&7;
    float rm[4], rz[4];
    #pragma unroll
    for (int rr = 0; rr < 4; rr++){
        rm[rr] = g_rmax[b*LD + m0 + sr + (rr<<5)];
        rz[rr] = g_rz  [b*LD + m0 + sr + (rr<<5)];
    }
    float c[4][4][4] = {};
    for (int kk = 0; kk < LD; kk += 32){
        #pragma unroll
        for (int rr = 0; rr < 4; rr++){
            int r = sr + (rr<<5);
            float4 v = *(const float4*)&S[(size_t)(m0+r)*LD + kk + (cg<<2)];
            int off = r*36 + ((cg ^ ((r>>3)&3))<<2);
            uint4 o;
            o.x = f2tf(__expf(v.x - rm[rr]) * rz[rr]);
            o.y = f2tf(__expf(v.y - rm[rr]) * rz[rr]);
            o.z = f2tf(__expf(v.z - rm[rr]) * rz[rr]);
            o.w = f2tf(__expf(v.w - rm[rr]) * rz[rr]);
            *(uint4*)&sA[off] = o;
        }
        stage_T(sB, Bg + (size_t)kk*LD + n0, tid);
        __syncthreads();
        compute_chunk36(c, uA, uB, wm0, wn0, lane);
        __syncthreads();
    }
    #pragma unroll
    for (int mt = 0; mt < 4; mt++){
        int row = m0 + wm0 + (mt<<4) + (lane>>2);
        #pragma unroll
        for (int nt = 0; nt < 4; nt++){
            int col = n0 + wn0 + (nt<<3) + ((lane&3)<<1);
            *(float2*)&C[(size_t)row*LD + col]     = make_float2(c[mt][nt][0], c[mt][nt][1]);
            *(float2*)&C[(size_t)(row+8)*LD + col] = make_float2(c[mt][nt][2], c[mt][nt][3]);
        }
    }
}

// ---------------------------------------------------------------------------
// Kernel 3b: weighted_i = softmax_col(S)^T @ I  (A: exp + transpose-staged from S)
// ---------------------------------------------------------------------------
__global__ __launch_bounds__(256,2) void k_wi(const float* __restrict__ Ig)
{
    __shared__ float sA[128*36], sB[128*36];
    const int b  = blockIdx.z;
    const int m0 = blockIdx.y*128, n0 = blockIdx.x*128; // m = j, n = d
    const float* S  = g_S + (size_t)b*LD*LD;
    const float* Bg = Ig  + (size_t)b*LD*LD;
    float*       C  = g_wi + (size_t)b*LD*LD;
    const int tid = threadIdx.x, lane = tid&31, warp = tid>>5;
    const int wm0 = (warp&1)<<6, wn0 = (warp>>1)<<5;
    unsigned uA = (unsigned)__cvta_generic_to_shared(sA);
    unsigned uB = (unsigned)__cvta_generic_to_shared(sB);
    const int l = tid&31, kb = tid>>5;
    const int n = l<<2, sw = (n>>3)&3;   // n = local j column
    float4 cm = *(const float4*)&g_cmax[b*LD + m0 + n];
    float4 cz = *(const float4*)&g_cz  [b*LD + m0 + n];
    float c[4][4][4] = {};
    for (int kk = 0; kk < LD; kk += 32){
        #pragma unroll
        for (int ki = 0; ki < 4; ki++){
            int k = kb + (ki<<3);
            float4 v = *(const float4*)&S[(size_t)(kk+k)*LD + m0 + n];
            int g = (k>>2) ^ sw;
            float* p = sA + n*36 + (g<<2) + (k&3);
            p[0]   = __uint_as_float(f2tf(__expf(v.x - cm.x) * cz.x));
            p[36]  = __uint_as_float(f2tf(__expf(v.y - cm.y) * cz.y));
            p[72]  = __uint_as_float(f2tf(__expf(v.z - cm.z) * cz.z));
            p[108] = __uint_as_float(f2tf(__expf(v.w - cm.w) * cz.w));
        }
        stage_T(sB, Bg + (size_t)kk*LD + n0, tid);
        __syncthreads();
        compute_chunk36(c, uA, uB, wm0, wn0, lane);
        __syncthreads();
    }
    #pragma unroll
    for (int mt = 0; mt < 4; mt++){
        int row = m0 + wm0 + (mt<<4) + (lane>>2);
        #pragma unroll
        for (int nt = 0; nt < 4; nt++){
            int col = n0 + wn0 + (nt<<3) + ((lane&3)<<1);
            *(float2*)&C[(size_t)row*LD + col]     = make_float2(c[mt][nt][0], c[mt][nt][1]);
            *(float2*)&C[(size_t)(row+8)*LD + col] = make_float2(c[mt][nt][2], c[mt][nt][3]);
        }
    }
}

// ---------------------------------------------------------------------------
// Kernel 4: fused |x - w| @ W + bias -> tanh -> column sum over 512 rows.
// which=0: x=I, w=g_wj -> g_oi ; which=1: x=J, w=g_wi -> g_oj.
// Block owns 128 output columns for one (b, which); loops all 4 m-blocks.
// ---------------------------------------------------------------------------
__global__ __launch_bounds__(256,2) void k_agg(const float* __restrict__ I,
                                               const float* __restrict__ J,
                                               const float* __restrict__ W,
                                               const float* __restrict__ bias)
{
    __shared__ float sA[128*36], sB[128*36];
    __shared__ float red[2][128];
    const int b = blockIdx.y, which = blockIdx.z;
    const int n0 = blockIdx.x*128;
    const float* P1 = (which ? J    : I   ) + (size_t)b*LD*LD;
    const float* P2 = (which ? g_wi : g_wj) + (size_t)b*LD*LD;
    float* Og       = (which ? g_oj : g_oi) + b*LD;
    const int tid = threadIdx.x, lane = tid&31, warp = tid>>5;
    const int wm0 = (warp&1)<<6, wn0 = (warp>>1)<<5;
    unsigned uA = (unsigned)__cvta_generic_to_shared(sA);
    unsigned uB = (unsigned)__cvta_generic_to_shared(sB);
    const int sr = tid>>3, cg = tid&7;
    float bia[4][2];
    #pragma unroll
    for (int nt = 0; nt < 4; nt++){
        int col = n0 + wn0 + (nt<<3) + ((lane&3)<<1);
        bia[nt][0] = bias[col]; bia[nt][1] = bias[col+1];
    }
    float csum[4][2] = {};
    for (int mb = 0; mb < 4; mb++){
        const int mo = mb<<7;
        float c[4][4][4] = {};
        for (int kk = 0; kk < LD; kk += 32){
            #pragma unroll
            for (int rr = 0; rr < 4; rr++){
                int r = sr + (rr<<5);
                float4 x = *(const float4*)&P1[(size_t)(mo+r)*LD + kk + (cg<<2)];
                float4 w = *(const float4*)&P2[(size_t)(mo+r)*LD + kk + (cg<<2)];
                int off = r*36 + ((cg ^ ((r>>3)&3))<<2);
                uint4 o;
                o.x = f2tf(fabsf(x.x - w.x));
                o.y = f2tf(fabsf(x.y - w.y));
                o.z = f2tf(fabsf(x.z - w.z));
                o.w = f2tf(fabsf(x.w - w.w));
                *(uint4*)&sA[off] = o;
            }
            stage_T(sB, W + (size_t)kk*LD + n0, tid);
            __syncthreads();
            compute_chunk36(c, uA, uB, wm0, wn0, lane);
            __syncthreads();
        }
        #pragma unroll
        for (int mt = 0; mt < 4; mt++)
            #pragma unroll
            for (int nt = 0; nt < 4; nt++){
                csum[nt][0] += tanhf(c[mt][nt][0] + bia[nt][0]) + tanhf(c[mt][nt][2] + bia[nt][0]);
                csum[nt][1] += tanhf(c[mt][nt][1] + bia[nt][1]) + tanhf(c[mt][nt][3] + bia[nt][1]);
            }
    }
    // reduce over the 8 row-groups within the warp (lanes differing in bits 2..4)
    #pragma unroll
    for (int nt = 0; nt < 4; nt++)
        #pragma unroll
        for (int u = 0; u < 2; u++){
            float s = csum[nt][u];
            s += __shfl_xor_sync(0xffffffffu, s, 4);
            s += __shfl_xor_sync(0xffffffffu, s, 8);
            s += __shfl_xor_sync(0xffffffffu, s, 16);
            csum[nt][u] = s;
        }
    if ((lane>>2) == 0){
        #pragma unroll
        for (int nt = 0; nt < 4; nt++){
            int col = wn0 + (nt<<3) + ((lane&3)<<1);
            red[warp&1][col]   = csum[nt][0];
            red[warp&1][col+1] = csum[nt][1];
        }
    }
    __syncthreads();
    if (tid < 128) Og[n0 + tid] = red[0][tid] + red[1][tid];
}

// ---------------------------------------------------------------------------
__global__ void k_combine(float* __restrict__ out)
{
    const int idx = blockIdx.x * 256 + threadIdx.x;
    out[idx] = (g_oi[idx] + g_oj[idx]) * (0.5f / 512.0f);
}

// ---------------------------------------------------------------------------
extern "C" void kernel_launch(void* const* d_in, const int* in_sizes, int n_in,
                              void* d_out, int out_size)
{
    (void)in_sizes; (void)n_in; (void)out_size;
    const float* I    = (const float*)d_in[0];
    const float* J    = (const float*)d_in[1];
    const float* W    = (const float*)d_in[2];
    const float* bias = (const float*)d_in[3];
    float* out = (float*)d_out;

    dim3 gg(4, 4, NB);
    k_scores  <<<gg, 256>>>(I, J);
    k_rowstats<<<NB * LD / 8, 256>>>();
    k_colstats<<<dim3(4, NB), 128>>>();
    k_wj      <<<gg, 256>>>(J);
    k_wi      <<<gg, 256>>>(I);
    k_agg     <<<dim3(4, NB, 2), 256>>>(I, J, W, bias);
    k_combine <<<64, 256>>>(out);
}

// round 4
// speedup vs baseline: 3.0378x; 1.4858x over previous
#include <cuda_runtime.h>
#include <math.h>

#define LD 512
#define NB 32
#define NBLD (NB*LD)

// ------------------------- scratch (device globals) -------------------------
__device__ float g_S [(size_t)NB*LD*LD];
__device__ float g_ST[(size_t)NB*LD*LD];
__device__ float g_wj[(size_t)NB*LD*LD];
__device__ float g_wi[(size_t)NB*LD*LD];
__device__ float g_jT[(size_t)NB*LD*LD];
__device__ float g_iT[(size_t)NB*LD*LD];
__device__ float g_wT[(size_t)LD*LD];
__device__ float g_rmax[NBLD], g_rz[NBLD], g_cmax[NBLD], g_cz[NBLD];
__device__ float g_part[2*NB*4*LD];

// ------------------------- helpers ------------------------------------------
__device__ __forceinline__ unsigned f2tf(float x){
    unsigned r; asm("cvt.rna.tf32.f32 %0, %1;" : "=r"(r) : "f"(x)); return r;
}
__device__ __forceinline__ float tanh_ap(float x){
    float r; asm("tanh.approx.f32 %0, %1;" : "=f"(r) : "f"(x)); return r;
}
__device__ __forceinline__ void mma8(float* c, unsigned a0,unsigned a1,unsigned a2,unsigned a3,
                                     unsigned b0,unsigned b1){
    asm volatile("mma.sync.aligned.m16n8k8.row.col.f32.tf32.tf32.f32 "
        "{%0,%1,%2,%3}, {%4,%5,%6,%7}, {%8,%9}, {%0,%1,%2,%3};"
        : "+f"(c[0]),"+f"(c[1]),"+f"(c[2]),"+f"(c[3])
        : "r"(a0),"r"(a1),"r"(a2),"r"(a3),"r"(b0),"r"(b1));
}
__device__ __forceinline__ void ldmx4(unsigned* r, unsigned addr){
    asm volatile("ldmatrix.sync.aligned.m8n8.x4.shared.b16 {%0,%1,%2,%3}, [%4];"
        : "=r"(r[0]),"=r"(r[1]),"=r"(r[2]),"=r"(r[3]) : "r"(addr));
}
__device__ __forceinline__ void cpasync16(unsigned saddr, const float* g){
    asm volatile("cp.async.cg.shared.global [%0], [%1], 16;" :: "r"(saddr), "l"(g));
}
__device__ __forceinline__ void cpcommit(){ asm volatile("cp.async.commit_group;"); }
template<int N> __device__ __forceinline__ void cpwait(){
    asm volatile("cp.async.wait_group %0;" :: "n"(N));
}

// smem tile layout: 128 rows x 32 floats, 16B group g swizzled by g ^ (row & 7)
__device__ __forceinline__ void stage_cp(unsigned sbase, const float* g, int tid){
    #pragma unroll
    for (int q = 0; q < 4; q++){
        int idx = tid + (q << 8);
        int r = idx >> 3, gs = idx & 7;
        cpasync16(sbase + (unsigned)(((r << 5) + ((gs ^ (r & 7)) << 2)) << 2),
                  g + (size_t)r * LD + (gs << 2));
    }
}
__device__ __forceinline__ unsigned a_addr32(unsigned base, int row0, int ks, int lane){
    int sub = lane >> 3;
    int r = row0 + (lane & 7) + ((sub & 1) << 3);
    int kg = (ks << 1) + (sub >> 1);
    int g = kg ^ (r & 7);
    return base + (unsigned)(((r << 5) + (g << 2)) << 2);
}
__device__ __forceinline__ unsigned b_addr32(unsigned base, int n0, int ks, int lane){
    int sub = lane >> 3;
    int n = n0 + (lane & 7) + ((sub >> 1) << 3);
    int kg = (ks << 1) + (sub & 1);
    int g = kg ^ (n & 7);
    return base + (unsigned)(((n << 5) + (g << 2)) << 2);
}

#define TILE_B 16384   // bytes per 128x32 fp32 tile

// ---------------------------------------------------------------------------
// k_T: 512x512 transpose (batched); which selects destination device global.
// ---------------------------------------------------------------------------
__global__ __launch_bounds__(256) void k_T(const float* __restrict__ src, int which)
{
    __shared__ float s[64][65];
    const int b = blockIdx.z;
    float* dst = (which == 0 ? g_jT : (which == 1 ? g_iT : g_wT)) + (size_t)b*LD*LD;
    const float* sp = src + (size_t)b*LD*LD;
    const int r0 = blockIdx.y*64, c0 = blockIdx.x*64;
    const int tid = threadIdx.x;
    const int tr = tid >> 4, tc = (tid & 15) << 2;
    #pragma unroll
    for (int rr = 0; rr < 4; rr++){
        int r = tr + (rr << 4);
        float4 v = *(const float4*)&sp[(size_t)(r0 + r)*LD + c0 + tc];
        s[tc+0][r] = v.x; s[tc+1][r] = v.y; s[tc+2][r] = v.z; s[tc+3][r] = v.w;
    }
    __syncthreads();
    #pragma unroll
    for (int rr = 0; rr < 4; rr++){
        int r = tr + (rr << 4);
        float4 w = make_float4(s[r][tc], s[r][tc+1], s[r][tc+2], s[r][tc+3]);
        *(float4*)&dst[(size_t)(c0 + r)*LD + r0 + tc] = w;
    }
}

// ---------------------------------------------------------------------------
// k_scores: S = I @ J^T with 3xTF32; writes S and S^T. Pipelined cp.async.
// 8 warps, warp tile 64x32. BM=BN=128, BK=32.
// ---------------------------------------------------------------------------
__global__ __launch_bounds__(256,2) void k_scores(const float* __restrict__ I,
                                                  const float* __restrict__ J)
{
    extern __shared__ float smem[];
    unsigned su = (unsigned)__cvta_generic_to_shared(smem);
    const int b = blockIdx.z, m0 = blockIdx.y*128, n0 = blockIdx.x*128;
    const float* A = I + (size_t)b*LD*LD + (size_t)m0*LD;
    const float* B = J + (size_t)b*LD*LD + (size_t)n0*LD;
    float* C  = g_S  + (size_t)b*LD*LD;
    float* CT = g_ST + (size_t)b*LD*LD;
    const int tid = threadIdx.x, lane = tid & 31, warp = tid >> 5;
    const int wm0 = (warp & 1) << 6, wn0 = (warp >> 1) << 5;
    float c[4][4][4] = {};

    stage_cp(su, A, tid); stage_cp(su + 2*TILE_B, B, tid); cpcommit();
    for (int ch = 0; ch < 16; ch++){
        int st = ch & 1, nx = st ^ 1;
        if (ch < 15){
            stage_cp(su + nx*TILE_B, A + (ch+1)*32, tid);
            stage_cp(su + 2*TILE_B + nx*TILE_B, B + (ch+1)*32, tid);
            cpcommit();
            cpwait<1>();
        } else cpwait<0>();
        __syncthreads();
        unsigned uA = su + st*TILE_B, uB = su + 2*TILE_B + st*TILE_B;
        #pragma unroll
        for (int ks = 0; ks < 4; ks++){
            unsigned braw[2][4], bh[2][4], bl[2][4];
            ldmx4(braw[0], b_addr32(uB, wn0,    ks, lane));
            ldmx4(braw[1], b_addr32(uB, wn0+16, ks, lane));
            #pragma unroll
            for (int p = 0; p < 2; p++)
                #pragma unroll
                for (int z = 0; z < 4; z++){
                    float v = __uint_as_float(braw[p][z]);
                    bh[p][z] = f2tf(v);
                    bl[p][z] = f2tf(v - __uint_as_float(bh[p][z]));
                }
            #pragma unroll
            for (int mt = 0; mt < 4; mt++){
                unsigned araw[4], ah[4], al[4];
                ldmx4(araw, a_addr32(uA, wm0 + (mt<<4), ks, lane));
                #pragma unroll
                for (int z = 0; z < 4; z++){
                    float v = __uint_as_float(araw[z]);
                    ah[z] = f2tf(v);
                    al[z] = f2tf(v - __uint_as_float(ah[z]));
                }
                #pragma unroll
                for (int nt = 0; nt < 4; nt++){
                    int p = nt >> 1, q = (nt & 1) << 1;
                    mma8(c[mt][nt], ah[0],ah[1],ah[2],ah[3], bh[p][q], bh[p][q+1]);
                    mma8(c[mt][nt], ah[0],ah[1],ah[2],ah[3], bl[p][q], bl[p][q+1]);
                    mma8(c[mt][nt], al[0],al[1],al[2],al[3], bh[p][q], bh[p][q+1]);
                }
            }
        }
        __syncthreads();
    }
    // epilogue: S row-major
    #pragma unroll
    for (int mt = 0; mt < 4; mt++){
        int row = m0 + wm0 + (mt<<4) + (lane>>2);
        #pragma unroll
        for (int nt = 0; nt < 4; nt++){
            int col = n0 + wn0 + (nt<<3) + ((lane&3)<<1);
            *(float2*)&C[(size_t)row*LD + col]     = make_float2(c[mt][nt][0], c[mt][nt][1]);
            *(float2*)&C[(size_t)(row+8)*LD + col] = make_float2(c[mt][nt][2], c[mt][nt][3]);
        }
    }
    // epilogue: S^T via smem transpose, two 64-col halves
    const int wh = wn0 >> 6;
    for (int h = 0; h < 2; h++){
        __syncthreads();
        if (wh == h){
            #pragma unroll
            for (int mt = 0; mt < 4; mt++){
                int rw = wm0 + (mt<<4) + (lane>>2);
                #pragma unroll
                for (int nt = 0; nt < 4; nt++){
                    int cl = wn0 - (h<<6) + (nt<<3) + ((lane&3)<<1);
                    smem[cl*132 + rw]       = c[mt][nt][0];
                    smem[(cl+1)*132 + rw]   = c[mt][nt][1];
                    smem[cl*132 + rw + 8]   = c[mt][nt][2];
                    smem[(cl+1)*132 + rw+8] = c[mt][nt][3];
                }
            }
        }
        __syncthreads();
        #pragma unroll
        for (int w2 = 0; w2 < 8; w2++){
            int pos = tid + (w2 << 8);
            int orow = pos >> 5, oc = pos & 31;
            float4 v = *(float4*)&smem[orow*132 + (oc<<2)];
            *(float4*)&CT[(size_t)(n0 + (h<<6) + orow)*LD + m0 + (oc<<2)] = v;
        }
    }
}

// ---------------------------------------------------------------------------
// k_stats: warp-per-row max/sumexp on S (rows) and S^T (cols). Coalesced.
// ---------------------------------------------------------------------------
__global__ __launch_bounds__(256) void k_stats()
{
    const int idx  = blockIdx.x * 8 + (threadIdx.x >> 5);
    const int lane = threadIdx.x & 31;
    const bool cs  = idx >= NBLD;
    const int row  = cs ? idx - NBLD : idx;
    const float4* s = (const float4*)((cs ? g_ST : g_S) + (size_t)row * LD);
    float4 v[4];
    #pragma unroll
    for (int it = 0; it < 4; it++) v[it] = s[lane + (it<<5)];
    float mx = -1e30f;
    #pragma unroll
    for (int it = 0; it < 4; it++)
        mx = fmaxf(mx, fmaxf(fmaxf(v[it].x, v[it].y), fmaxf(v[it].z, v[it].w)));
    #pragma unroll
    for (int o = 16; o; o >>= 1) mx = fmaxf(mx, __shfl_xor_sync(0xffffffffu, mx, o));
    float sum = 0.f;
    #pragma unroll
    for (int it = 0; it < 4; it++)
        sum += __expf(v[it].x-mx)+__expf(v[it].y-mx)+__expf(v[it].z-mx)+__expf(v[it].w-mx);
    #pragma unroll
    for (int o = 16; o; o >>= 1) sum += __shfl_xor_sync(0xffffffffu, sum, o);
    if (lane == 0){
        if (cs){ g_cmax[row] = mx; g_cz[row] = 1.0f/sum; }
        else   { g_rmax[row] = mx; g_rz[row] = 1.0f/sum; }
    }
}

// ---------------------------------------------------------------------------
// k_wjwi: which=0: wj = rowsoftmax(S) @ J  (A=S,  B=J^T, stats rmax/rz)
//         which=1: wi = colsoftmax(S)^T @ I (A=S^T, B=I^T, stats cmax/cz)
// Warp tile 32x64 (exp redundancy 2x). Pipelined cp.async, exp in registers.
// ---------------------------------------------------------------------------
__global__ __launch_bounds__(256,2) void k_wjwi()
{
    extern __shared__ float smem[];
    unsigned su = (unsigned)__cvta_generic_to_shared(smem);
    const int z = blockIdx.z, b = z >> 1, which = z & 1;
    const int m0 = blockIdx.y*128, n0 = blockIdx.x*128;
    const float* A  = (which ? g_ST : g_S ) + (size_t)b*LD*LD + (size_t)m0*LD;
    const float* B  = (which ? g_iT : g_jT) + (size_t)b*LD*LD + (size_t)n0*LD;
    float*       C  = (which ? g_wi : g_wj) + (size_t)b*LD*LD;
    const float* RM = (which ? g_cmax : g_rmax) + b*LD + m0;
    const float* RZ = (which ? g_cz   : g_rz  ) + b*LD + m0;
    const int tid = threadIdx.x, lane = tid & 31, warp = tid >> 5;
    const int wm0 = (warp & 3) << 5, wn0 = (warp >> 2) << 6;
    float rm[2][2], rz[2][2];
    #pragma unroll
    for (int mt = 0; mt < 2; mt++)
        #pragma unroll
        for (int u = 0; u < 2; u++){
            int r = wm0 + (mt<<4) + (lane>>2) + (u<<3);
            rm[mt][u] = RM[r]; rz[mt][u] = RZ[r];
        }
    float c[2][8][4] = {};

    stage_cp(su, A, tid); stage_cp(su + 2*TILE_B, B, tid); cpcommit();
    for (int ch = 0; ch < 16; ch++){
        int st = ch & 1, nx = st ^ 1;
        if (ch < 15){
            stage_cp(su + nx*TILE_B, A + (ch+1)*32, tid);
            stage_cp(su + 2*TILE_B + nx*TILE_B, B + (ch+1)*32, tid);
            cpcommit();
            cpwait<1>();
        } else cpwait<0>();
        __syncthreads();
        unsigned uA = su + st*TILE_B, uB = su + 2*TILE_B + st*TILE_B;
        #pragma unroll
        for (int ks = 0; ks < 4; ks++){
            unsigned braw[4][4];
            #pragma unroll
            for (int p = 0; p < 4; p++){
                ldmx4(braw[p], b_addr32(uB, wn0 + (p<<4), ks, lane));
                #pragma unroll
                for (int zz = 0; zz < 4; zz++)
                    braw[p][zz] = f2tf(__uint_as_float(braw[p][zz]));
            }
            #pragma unroll
            for (int mt = 0; mt < 2; mt++){
                unsigned ar[4], af[4];
                ldmx4(ar, a_addr32(uA, wm0 + (mt<<4), ks, lane));
                #pragma unroll
                for (int zz = 0; zz < 4; zz++)
                    af[zz] = f2tf(__expf(__uint_as_float(ar[zz]) - rm[mt][zz&1]) * rz[mt][zz&1]);
                #pragma unroll
                for (int nt = 0; nt < 8; nt++){
                    int p = nt >> 1, q = (nt & 1) << 1;
                    mma8(c[mt][nt], af[0],af[1],af[2],af[3], braw[p][q], braw[p][q+1]);
                }
            }
        }
        __syncthreads();
    }
    #pragma unroll
    for (int mt = 0; mt < 2; mt++){
        int row = m0 + wm0 + (mt<<4) + (lane>>2);
        #pragma unroll
        for (int nt = 0; nt < 8; nt++){
            int col = n0 + wn0 + (nt<<3) + ((lane&3)<<1);
            *(float2*)&C[(size_t)row*LD + col]     = make_float2(c[mt][nt][0], c[mt][nt][1]);
            *(float2*)&C[(size_t)(row+8)*LD + col] = make_float2(c[mt][nt][2], c[mt][nt][3]);
        }
    }
}

// ---------------------------------------------------------------------------
// k_agg: partial = colsum over 128 rows of tanh(|X - Wt| @ W_agg + bias).
// grid.x: (n0 4) x (mb 4); grid.y: batch; grid.z: which. Pipelined, 3 streams.
// ---------------------------------------------------------------------------
__global__ __launch_bounds__(256,2) void k_agg(const float* __restrict__ I,
                                               const float* __restrict__ J,
                                               const float* __restrict__ bias)
{
    extern __shared__ float smem[];
    unsigned su = (unsigned)__cvta_generic_to_shared(smem);
    const int bx = blockIdx.x, b = blockIdx.y, which = blockIdx.z;
    const int n0 = (bx & 3) << 7, mb = bx >> 2;
    const float* X = (which ? J : I)        + (size_t)b*LD*LD + (size_t)(mb<<7)*LD;
    const float* Wd = (which ? g_wi : g_wj) + (size_t)b*LD*LD + (size_t)(mb<<7)*LD;
    const float* Bm = g_wT + (size_t)n0*LD;
    float* Og = g_part + (size_t)((((which*NB) + b)<<2) + mb)*LD;
    const int tid = threadIdx.x, lane = tid & 31, warp = tid >> 5;
    const int wm0 = (warp & 1) << 6, wn0 = (warp >> 1) << 5;
    float bia[4][2];
    #pragma unroll
    for (int nt = 0; nt < 4; nt++){
        int col = n0 + wn0 + (nt<<3) + ((lane&3)<<1);
        bia[nt][0] = bias[col]; bia[nt][1] = bias[col+1];
    }
    float c[4][4][4] = {};

    stage_cp(su, X, tid); stage_cp(su + 2*TILE_B, Wd, tid);
    stage_cp(su + 4*TILE_B, Bm, tid); cpcommit();
    for (int ch = 0; ch < 16; ch++){
        int st = ch & 1, nx = st ^ 1;
        if (ch < 15){
            stage_cp(su + nx*TILE_B,            X  + (ch+1)*32, tid);
            stage_cp(su + 2*TILE_B + nx*TILE_B, Wd + (ch+1)*32, tid);
            stage_cp(su + 4*TILE_B + nx*TILE_B, Bm + (ch+1)*32, tid);
            cpcommit();
            cpwait<1>();
        } else cpwait<0>();
        __syncthreads();
        unsigned uX = su + st*TILE_B, uW = su + 2*TILE_B + st*TILE_B,
                 uB = su + 4*TILE_B + st*TILE_B;
        #pragma unroll
        for (int ks = 0; ks < 4; ks++){
            unsigned braw[2][4];
            ldmx4(braw[0], b_addr32(uB, wn0,    ks, lane));
            ldmx4(braw[1], b_addr32(uB, wn0+16, ks, lane));
            #pragma unroll
            for (int p = 0; p < 2; p++)
                #pragma unroll
                for (int zz = 0; zz < 4; zz++)
                    braw[p][zz] = f2tf(__uint_as_float(braw[p][zz]));
            #pragma unroll
            for (int mt = 0; mt < 4; mt++){
                unsigned xr[4], wr[4], d[4];
                ldmx4(xr, a_addr32(uX, wm0 + (mt<<4), ks, lane));
                ldmx4(wr, a_addr32(uW, wm0 + (mt<<4), ks, lane));
                #pragma unroll
                for (int zz = 0; zz < 4; zz++)
                    d[zz] = f2tf(fabsf(__uint_as_float(xr[zz]) - __uint_as_float(wr[zz])));
                #pragma unroll
                for (int nt = 0; nt < 4; nt++){
                    int p = nt >> 1, q = (nt & 1) << 1;
                    mma8(c[mt][nt], d[0],d[1],d[2],d[3], braw[p][q], braw[p][q+1]);
                }
            }
        }
        __syncthreads();
    }
    // tanh + column-sum epilogue
    float csum[4][2] = {};
    #pragma unroll
    for (int mt = 0; mt < 4; mt++)
        #pragma unroll
        for (int nt = 0; nt < 4; nt++){
            csum[nt][0] += tanh_ap(c[mt][nt][0] + bia[nt][0]) + tanh_ap(c[mt][nt][2] + bia[nt][0]);
            csum[nt][1] += tanh_ap(c[mt][nt][1] + bia[nt][1]) + tanh_ap(c[mt][nt][3] + bia[nt][1]);
        }
    #pragma unroll
    for (int nt = 0; nt < 4; nt++)
        #pragma unroll
        for (int u = 0; u < 2; u++){
            float s = csum[nt][u];
            s += __shfl_xor_sync(0xffffffffu, s, 4);
            s += __shfl_xor_sync(0xffffffffu, s, 8);
            s += __shfl_xor_sync(0xffffffffu, s, 16);
            csum[nt][u] = s;
        }
    float* red = smem; // [2][128], reuse pipeline smem (free after last sync)
    if ((lane >> 2) == 0){
        #pragma unroll
        for (int nt = 0; nt < 4; nt++){
            int col = wn0 + (nt<<3) + ((lane&3)<<1);
            red[(warp&1)*128 + col]     = csum[nt][0];
            red[(warp&1)*128 + col + 1] = csum[nt][1];
        }
    }
    __syncthreads();
    if (tid < 128) Og[n0 + tid] = red[tid] + red[128 + tid];
}

// ---------------------------------------------------------------------------
__global__ void k_combine(float* __restrict__ out)
{
    const int idx = blockIdx.x * 256 + threadIdx.x;
    const int b = idx >> 9, h = idx & 511;
    float s = 0.f;
    #pragma unroll
    for (int w = 0; w < 2; w++)
        #pragma unroll
        for (int mb = 0; mb < 4; mb++)
            s += g_part[(size_t)((((w*NB) + b)<<2) + mb)*LD + h];
    out[idx] = s * (0.5f / 512.0f);
}

// ---------------------------------------------------------------------------
extern "C" void kernel_launch(void* const* d_in, const int* in_sizes, int n_in,
                              void* d_out, int out_size)
{
    (void)in_sizes; (void)n_in; (void)out_size;
    const float* I    = (const float*)d_in[0];
    const float* J    = (const float*)d_in[1];
    const float* W    = (const float*)d_in[2];
    const float* bias = (const float*)d_in[3];
    float* out = (float*)d_out;

    cudaFuncSetAttribute(k_scores, cudaFuncAttributeMaxDynamicSharedMemorySize, 4*TILE_B);
    cudaFuncSetAttribute(k_wjwi,   cudaFuncAttributeMaxDynamicSharedMemorySize, 4*TILE_B);
    cudaFuncSetAttribute(k_agg,    cudaFuncAttributeMaxDynamicSharedMemorySize, 6*TILE_B);

    k_T      <<<dim3(8,8,NB), 256>>>(J, 0);
    k_T      <<<dim3(8,8,NB), 256>>>(I, 1);
    k_T      <<<dim3(8,8,1),  256>>>(W, 2);
    k_scores <<<dim3(4,4,NB),   256, 4*TILE_B>>>(I, J);
    k_stats  <<<2*NBLD/8,       256>>>();
    k_wjwi   <<<dim3(4,4,2*NB), 256, 4*TILE_B>>>();
    k_agg    <<<dim3(16,NB,2),  256, 6*TILE_B>>>(I, J, bias);
    k_combine<<<64, 256>>>(out);
}

// round 5
// speedup vs baseline: 3.8771x; 1.2763x over previous
#include <cuda_runtime.h>
#include <math.h>

#define LD 512
#define NB 32
#define NBLD (NB*LD)

// ------------------------- scratch (device globals) -------------------------
__device__ float g_S [(size_t)NB*LD*LD];
__device__ float g_ST[(size_t)NB*LD*LD];
__device__ float g_wj[(size_t)NB*LD*LD];
__device__ float g_wi[(size_t)NB*LD*LD];
__device__ float g_jT[(size_t)NB*LD*LD];
__device__ float g_iT[(size_t)NB*LD*LD];
__device__ float g_wT[(size_t)LD*LD];
__device__ float g_rmax[NBLD], g_rz[NBLD], g_cmax[NBLD], g_cz[NBLD];
__device__ float g_prm[NB*4*LD], g_prs[NB*4*LD];   // row-softmax partials (per n-tile)
__device__ float g_pcm[NB*4*LD], g_pcs[NB*4*LD];   // col-softmax partials (per m-tile)
__device__ float g_part[2*NB*4*LD];

// ------------------------- helpers ------------------------------------------
__device__ __forceinline__ unsigned f2tf(float x){
    unsigned r; asm("cvt.rna.tf32.f32 %0, %1;" : "=r"(r) : "f"(x)); return r;
}
__device__ __forceinline__ float tanh_ap(float x){
    float r; asm("tanh.approx.f32 %0, %1;" : "=f"(r) : "f"(x)); return r;
}
__device__ __forceinline__ void mma8(float* c, unsigned a0,unsigned a1,unsigned a2,unsigned a3,
                                     unsigned b0,unsigned b1){
    asm volatile("mma.sync.aligned.m16n8k8.row.col.f32.tf32.tf32.f32 "
        "{%0,%1,%2,%3}, {%4,%5,%6,%7}, {%8,%9}, {%0,%1,%2,%3};"
        : "+f"(c[0]),"+f"(c[1]),"+f"(c[2]),"+f"(c[3])
        : "r"(a0),"r"(a1),"r"(a2),"r"(a3),"r"(b0),"r"(b1));
}
__device__ __forceinline__ void ldmx4(unsigned* r, unsigned addr){
    asm volatile("ldmatrix.sync.aligned.m8n8.x4.shared.b16 {%0,%1,%2,%3}, [%4];"
        : "=r"(r[0]),"=r"(r[1]),"=r"(r[2]),"=r"(r[3]) : "r"(addr));
}
__device__ __forceinline__ void cpasync16(unsigned saddr, const float* g){
    asm volatile("cp.async.cg.shared.global [%0], [%1], 16;" :: "r"(saddr), "l"(g));
}
__device__ __forceinline__ void cpcommit(){ asm volatile("cp.async.commit_group;"); }
template<int N> __device__ __forceinline__ void cpwait(){
    asm volatile("cp.async.wait_group %0;" :: "n"(N));
}

// smem tile layout: 128 rows x 32 floats, 16B group g swizzled by g ^ (row & 7)
__device__ __forceinline__ void stage_cp(unsigned sbase, const float* g, int tid){
    #pragma unroll
    for (int q = 0; q < 4; q++){
        int idx = tid + (q << 8);
        int r = idx >> 3, gs = idx & 7;
        cpasync16(sbase + (unsigned)(((r << 5) + ((gs ^ (r & 7)) << 2)) << 2),
                  g + (size_t)r * LD + (gs << 2));
    }
}
__device__ __forceinline__ unsigned a_addr32(unsigned base, int row0, int ks, int lane){
    int sub = lane >> 3;
    int r = row0 + (lane & 7) + ((sub & 1) << 3);
    int kg = (ks << 1) + (sub >> 1);
    int g = kg ^ (r & 7);
    return base + (unsigned)(((r << 5) + (g << 2)) << 2);
}
__device__ __forceinline__ unsigned b_addr32(unsigned base, int n0, int ks, int lane){
    int sub = lane >> 3;
    int n = n0 + (lane & 7) + ((sub >> 1) << 3);
    int kg = (ks << 1) + (sub & 1);
    int g = kg ^ (n & 7);
    return base + (unsigned)(((n << 5) + (g << 2)) << 2);
}

#define TILE_B 16384   // bytes per 128x32 fp32 tile

// ---------------------------------------------------------------------------
// k_T: 512x512 transpose (batched)
// ---------------------------------------------------------------------------
__global__ __launch_bounds__(256) void k_T(const float* __restrict__ src, int which)
{
    __shared__ float s[64][65];
    const int b = blockIdx.z;
    float* dst = (which == 0 ? g_jT : (which == 1 ? g_iT : g_wT)) + (size_t)b*LD*LD;
    const float* sp = src + (size_t)b*LD*LD;
    const int r0 = blockIdx.y*64, c0 = blockIdx.x*64;
    const int tid = threadIdx.x;
    const int tr = tid >> 4, tc = (tid & 15) << 2;
    #pragma unroll
    for (int rr = 0; rr < 4; rr++){
        int r = tr + (rr << 4);
        float4 v = *(const float4*)&sp[(size_t)(r0 + r)*LD + c0 + tc];
        s[tc+0][r] = v.x; s[tc+1][r] = v.y; s[tc+2][r] = v.z; s[tc+3][r] = v.w;
    }
    __syncthreads();
    #pragma unroll
    for (int rr = 0; rr < 4; rr++){
        int r = tr + (rr << 4);
        float4 w = make_float4(s[r][tc], s[r][tc+1], s[r][tc+2], s[r][tc+3]);
        *(float4*)&dst[(size_t)(c0 + r)*LD + r0 + tc] = w;
    }
}

// ---------------------------------------------------------------------------
// k_scores: S = I @ J^T (single tf32), writes S + S^T + fused partial softmax
// stats (row partials over this CTA's 128 cols, col partials over 128 rows).
// 8 warps, warp tile 64x32. BM=BN=128, BK=32, double-buffered cp.async.
// ---------------------------------------------------------------------------
__global__ __launch_bounds__(256,2) void k_scores(const float* __restrict__ I,
                                                  const float* __restrict__ J)
{
    extern __shared__ float smem[];
    unsigned su = (unsigned)__cvta_generic_to_shared(smem);
    const int b = blockIdx.z, m0 = blockIdx.y*128, n0 = blockIdx.x*128;
    const float* A = I + (size_t)b*LD*LD + (size_t)m0*LD;
    const float* B = J + (size_t)b*LD*LD + (size_t)n0*LD;
    float* C  = g_S  + (size_t)b*LD*LD;
    float* CT = g_ST + (size_t)b*LD*LD;
    const int tid = threadIdx.x, lane = tid & 31, warp = tid >> 5;
    const int wm0 = (warp & 1) << 6, wn0 = (warp >> 1) << 5;
    float c[4][4][4] = {};

    stage_cp(su, A, tid); stage_cp(su + 2*TILE_B, B, tid); cpcommit();
    for (int ch = 0; ch < 16; ch++){
        int st = ch & 1, nx = st ^ 1;
        if (ch < 15){
            stage_cp(su + nx*TILE_B, A + (ch+1)*32, tid);
            stage_cp(su + 2*TILE_B + nx*TILE_B, B + (ch+1)*32, tid);
            cpcommit();
            cpwait<1>();
        } else cpwait<0>();
        __syncthreads();
        unsigned uA = su + st*TILE_B, uB = su + 2*TILE_B + st*TILE_B;
        #pragma unroll
        for (int ks = 0; ks < 4; ks++){
            unsigned braw[2][4];
            ldmx4(braw[0], b_addr32(uB, wn0,    ks, lane));
            ldmx4(braw[1], b_addr32(uB, wn0+16, ks, lane));
            #pragma unroll
            for (int p = 0; p < 2; p++)
                #pragma unroll
                for (int z = 0; z < 4; z++)
                    braw[p][z] = f2tf(__uint_as_float(braw[p][z]));
            #pragma unroll
            for (int mt = 0; mt < 4; mt++){
                unsigned af[4];
                ldmx4(af, a_addr32(uA, wm0 + (mt<<4), ks, lane));
                #pragma unroll
                for (int z = 0; z < 4; z++)
                    af[z] = f2tf(__uint_as_float(af[z]));
                #pragma unroll
                for (int nt = 0; nt < 4; nt++){
                    int p = nt >> 1, q = (nt & 1) << 1;
                    mma8(c[mt][nt], af[0],af[1],af[2],af[3], braw[p][q], braw[p][q+1]);
                }
            }
        }
        __syncthreads();
    }

    // --- epilogue 1: S row-major store ---
    #pragma unroll
    for (int mt = 0; mt < 4; mt++){
        int row = m0 + wm0 + (mt<<4) + (lane>>2);
        #pragma unroll
        for (int nt = 0; nt < 4; nt++){
            int col = n0 + wn0 + (nt<<3) + ((lane&3)<<1);
            *(float2*)&C[(size_t)row*LD + col]     = make_float2(c[mt][nt][0], c[mt][nt][1]);
            *(float2*)&C[(size_t)(row+8)*LD + col] = make_float2(c[mt][nt][2], c[mt][nt][3]);
        }
    }

    // --- epilogue 2: row-softmax partials over this CTA's 128 columns ---
    {
        float* prm = smem;          // [4][128]
        float* prs = smem + 512;    // [4][128]
        const int wn_idx = warp >> 1;
        #pragma unroll
        for (int mt = 0; mt < 4; mt++){
            float mx1 = -1e30f, mx2 = -1e30f;
            #pragma unroll
            for (int nt = 0; nt < 4; nt++){
                mx1 = fmaxf(mx1, fmaxf(c[mt][nt][0], c[mt][nt][1]));
                mx2 = fmaxf(mx2, fmaxf(c[mt][nt][2], c[mt][nt][3]));
            }
            #pragma unroll
            for (int o = 1; o <= 2; o <<= 1){
                mx1 = fmaxf(mx1, __shfl_xor_sync(0xffffffffu, mx1, o));
                mx2 = fmaxf(mx2, __shfl_xor_sync(0xffffffffu, mx2, o));
            }
            float s1 = 0.f, s2 = 0.f;
            #pragma unroll
            for (int nt = 0; nt < 4; nt++){
                s1 += __expf(c[mt][nt][0]-mx1) + __expf(c[mt][nt][1]-mx1);
                s2 += __expf(c[mt][nt][2]-mx2) + __expf(c[mt][nt][3]-mx2);
            }
            #pragma unroll
            for (int o = 1; o <= 2; o <<= 1){
                s1 += __shfl_xor_sync(0xffffffffu, s1, o);
                s2 += __shfl_xor_sync(0xffffffffu, s2, o);
            }
            if ((lane & 3) == 0){
                int r1 = wm0 + (mt<<4) + (lane>>2);
                prm[wn_idx*128 + r1]     = mx1; prs[wn_idx*128 + r1]     = s1;
                prm[wn_idx*128 + r1 + 8] = mx2; prs[wn_idx*128 + r1 + 8] = s2;
            }
        }
        __syncthreads();
        if (tid < 128){
            float M = -1e30f;
            #pragma unroll
            for (int w = 0; w < 4; w++) M = fmaxf(M, prm[w*128 + tid]);
            float S = 0.f;
            #pragma unroll
            for (int w = 0; w < 4; w++) S += prs[w*128 + tid] * __expf(prm[w*128 + tid] - M);
            int gi = (b*4 + blockIdx.x)*LD + m0 + tid;
            g_prm[gi] = M; g_prs[gi] = S;
        }
    }

    // --- epilogue 3: S^T store via smem + col-softmax partials ---
    const int wh = wn0 >> 6;
    const int mtile4 = (b*4 + blockIdx.y)*LD;
    for (int h = 0; h < 2; h++){
        __syncthreads();
        if (wh == h){
            #pragma unroll
            for (int mt = 0; mt < 4; mt++){
                int rw = wm0 + (mt<<4) + (lane>>2);
                #pragma unroll
                for (int nt = 0; nt < 4; nt++){
                    int cl = wn0 - (h<<6) + (nt<<3) + ((lane&3)<<1);
                    smem[cl*132 + rw]       = c[mt][nt][0];
                    smem[(cl+1)*132 + rw]   = c[mt][nt][1];
                    smem[cl*132 + rw + 8]   = c[mt][nt][2];
                    smem[(cl+1)*132 + rw+8] = c[mt][nt][3];
                }
            }
        }
        __syncthreads();
        #pragma unroll
        for (int w2 = 0; w2 < 8; w2++){
            int orow = warp + (w2 << 3);          // constant per warp
            float4 v = *(float4*)&smem[orow*132 + (lane<<2)];
            *(float4*)&CT[(size_t)(n0 + (h<<6) + orow)*LD + m0 + (lane<<2)] = v;
            // column partial over the CTA's 128 m-values (whole warp holds them)
            float mx = fmaxf(fmaxf(v.x, v.y), fmaxf(v.z, v.w));
            #pragma unroll
            for (int o = 16; o; o >>= 1) mx = fmaxf(mx, __shfl_xor_sync(0xffffffffu, mx, o));
            float s = __expf(v.x-mx)+__expf(v.y-mx)+__expf(v.z-mx)+__expf(v.w-mx);
            #pragma unroll
            for (int o = 16; o; o >>= 1) s += __shfl_xor_sync(0xffffffffu, s, o);
            if (lane == 0){
                int gi = mtile4 + n0 + (h<<6) + orow;
                g_pcm[gi] = mx; g_pcs[gi] = s;
            }
        }
    }
}

// ---------------------------------------------------------------------------
// k_finish: combine 4 tile-partials per row/col into final softmax stats.
// ---------------------------------------------------------------------------
__global__ __launch_bounds__(256) void k_finish()
{
    const int idx = blockIdx.x * 256 + threadIdx.x;    // [0, 2*NBLD)
    const bool cs = idx >= NBLD;
    const int r = cs ? idx - NBLD : idx;
    const int base = ((r >> 9) << 2)*LD + (r & 511);
    const float* PM = (cs ? g_pcm : g_prm) + base;
    const float* PS = (cs ? g_pcs : g_prs) + base;
    float M = -1e30f;
    #pragma unroll
    for (int t = 0; t < 4; t++) M = fmaxf(M, PM[t*LD]);
    float S = 0.f;
    #pragma unroll
    for (int t = 0; t < 4; t++) S += PS[t*LD] * __expf(PM[t*LD] - M);
    if (cs){ g_cmax[r] = M; g_cz[r] = 1.0f/S; }
    else   { g_rmax[r] = M; g_rz[r] = 1.0f/S; }
}

// ---------------------------------------------------------------------------
// k_wjwi: which=0: wj = rowsoftmax(S) @ J  (A=S,  B=J^T)
//         which=1: wi = colsoftmax(S)^T @ I (A=S^T, B=I^T)
// ---------------------------------------------------------------------------
__global__ __launch_bounds__(256,2) void k_wjwi()
{
    extern __shared__ float smem[];
    unsigned su = (unsigned)__cvta_generic_to_shared(smem);
    const int z = blockIdx.z, b = z >> 1, which = z & 1;
    const int m0 = blockIdx.y*128, n0 = blockIdx.x*128;
    const float* A  = (which ? g_ST : g_S ) + (size_t)b*LD*LD + (size_t)m0*LD;
    const float* B  = (which ? g_iT : g_jT) + (size_t)b*LD*LD + (size_t)n0*LD;
    float*       C  = (which ? g_wi : g_wj) + (size_t)b*LD*LD;
    const float* RM = (which ? g_cmax : g_rmax) + b*LD + m0;
    const float* RZ = (which ? g_cz   : g_rz  ) + b*LD + m0;
    const int tid = threadIdx.x, lane = tid & 31, warp = tid >> 5;
    const int wm0 = (warp & 3) << 5, wn0 = (warp >> 2) << 6;
    float rm[2][2], rz[2][2];
    #pragma unroll
    for (int mt = 0; mt < 2; mt++)
        #pragma unroll
        for (int u = 0; u < 2; u++){
            int r = wm0 + (mt<<4) + (lane>>2) + (u<<3);
            rm[mt][u] = RM[r]; rz[mt][u] = RZ[r];
        }
    float c[2][8][4] = {};

    stage_cp(su, A, tid); stage_cp(su + 2*TILE_B, B, tid); cpcommit();
    for (int ch = 0; ch < 16; ch++){
        int st = ch & 1, nx = st ^ 1;
        if (ch < 15){
            stage_cp(su + nx*TILE_B, A + (ch+1)*32, tid);
            stage_cp(su + 2*TILE_B + nx*TILE_B, B + (ch+1)*32, tid);
            cpcommit();
            cpwait<1>();
        } else cpwait<0>();
        __syncthreads();
        unsigned uA = su + st*TILE_B, uB = su + 2*TILE_B + st*TILE_B;
        #pragma unroll
        for (int ks = 0; ks < 4; ks++){
            unsigned braw[4][4];
            #pragma unroll
            for (int p = 0; p < 4; p++){
                ldmx4(braw[p], b_addr32(uB, wn0 + (p<<4), ks, lane));
                #pragma unroll
                for (int zz = 0; zz < 4; zz++)
                    braw[p][zz] = f2tf(__uint_as_float(braw[p][zz]));
            }
            #pragma unroll
            for (int mt = 0; mt < 2; mt++){
                unsigned ar[4], af[4];
                ldmx4(ar, a_addr32(uA, wm0 + (mt<<4), ks, lane));
                #pragma unroll
                for (int zz = 0; zz < 4; zz++)
                    af[zz] = f2tf(__expf(__uint_as_float(ar[zz]) - rm[mt][zz&1]) * rz[mt][zz&1]);
                #pragma unroll
                for (int nt = 0; nt < 8; nt++){
                    int p = nt >> 1, q = (nt & 1) << 1;
                    mma8(c[mt][nt], af[0],af[1],af[2],af[3], braw[p][q], braw[p][q+1]);
                }
            }
        }
        __syncthreads();
    }
    #pragma unroll
    for (int mt = 0; mt < 2; mt++){
        int row = m0 + wm0 + (mt<<4) + (lane>>2);
        #pragma unroll
        for (int nt = 0; nt < 8; nt++){
            int col = n0 + wn0 + (nt<<3) + ((lane&3)<<1);
            *(float2*)&C[(size_t)row*LD + col]     = make_float2(c[mt][nt][0], c[mt][nt][1]);
            *(float2*)&C[(size_t)(row+8)*LD + col] = make_float2(c[mt][nt][2], c[mt][nt][3]);
        }
    }
}

// ---------------------------------------------------------------------------
// k_agg: partial = colsum over 128 rows of tanh(|X - Wt| @ W_agg + bias).
// ---------------------------------------------------------------------------
__global__ __launch_bounds__(256,2) void k_agg(const float* __restrict__ I,
                                               const float* __restrict__ J,
                                               const float* __restrict__ bias)
{
    extern __shared__ float smem[];
    unsigned su = (unsigned)__cvta_generic_to_shared(smem);
    const int bx = blockIdx.x, b = blockIdx.y, which = blockIdx.z;
    const int n0 = (bx & 3) << 7, mb = bx >> 2;
    const float* X = (which ? J : I)        + (size_t)b*LD*LD + (size_t)(mb<<7)*LD;
    const float* Wd = (which ? g_wi : g_wj) + (size_t)b*LD*LD + (size_t)(mb<<7)*LD;
    const float* Bm = g_wT + (size_t)n0*LD;
    float* Og = g_part + (size_t)((((which*NB) + b)<<2) + mb)*LD;
    const int tid = threadIdx.x, lane = tid & 31, warp = tid >> 5;
    const int wm0 = (warp & 1) << 6, wn0 = (warp >> 1) << 5;
    float bia[4][2];
    #pragma unroll
    for (int nt = 0; nt < 4; nt++){
        int col = n0 + wn0 + (nt<<3) + ((lane&3)<<1);
        bia[nt][0] = bias[col]; bia[nt][1] = bias[col+1];
    }
    float c[4][4][4] = {};

    stage_cp(su, X, tid); stage_cp(su + 2*TILE_B, Wd, tid);
    stage_cp(su + 4*TILE_B, Bm, tid); cpcommit();
    for (int ch = 0; ch < 16; ch++){
        int st = ch & 1, nx = st ^ 1;
        if (ch < 15){
            stage_cp(su + nx*TILE_B,            X  + (ch+1)*32, tid);
            stage_cp(su + 2*TILE_B + nx*TILE_B, Wd + (ch+1)*32, tid);
            stage_cp(su + 4*TILE_B + nx*TILE_B, Bm + (ch+1)*32, tid);
            cpcommit();
            cpwait<1>();
        } else cpwait<0>();
        __syncthreads();
        unsigned uX = su + st*TILE_B, uW = su + 2*TILE_B + st*TILE_B,
                 uB = su + 4*TILE_B + st*TILE_B;
        #pragma unroll
        for (int ks = 0; ks < 4; ks++){
            unsigned braw[2][4];
            ldmx4(braw[0], b_addr32(uB, wn0,    ks, lane));
            ldmx4(braw[1], b_addr32(uB, wn0+16, ks, lane));
            #pragma unroll
            for (int p = 0; p < 2; p++)
                #pragma unroll
                for (int zz = 0; zz < 4; zz++)
                    braw[p][zz] = f2tf(__uint_as_float(braw[p][zz]));
            #pragma unroll
            for (int mt = 0; mt < 4; mt++){
                unsigned xr[4], wr[4], d[4];
                ldmx4(xr, a_addr32(uX, wm0 + (mt<<4), ks, lane));
                ldmx4(wr, a_addr32(uW, wm0 + (mt<<4), ks, lane));
                #pragma unroll
                for (int zz = 0; zz < 4; zz++)
                    d[zz] = f2tf(fabsf(__uint_as_float(xr[zz]) - __uint_as_float(wr[zz])));
                #pragma unroll
                for (int nt = 0; nt < 4; nt++){
                    int p = nt >> 1, q = (nt & 1) << 1;
                    mma8(c[mt][nt], d[0],d[1],d[2],d[3], braw[p][q], braw[p][q+1]);
                }
            }
        }
        __syncthreads();
    }
    float csum[4][2] = {};
    #pragma unroll
    for (int mt = 0; mt < 4; mt++)
        #pragma unroll
        for (int nt = 0; nt < 4; nt++){
            csum[nt][0] += tanh_ap(c[mt][nt][0] + bia[nt][0]) + tanh_ap(c[mt][nt][2] + bia[nt][0]);
            csum[nt][1] += tanh_ap(c[mt][nt][1] + bia[nt][1]) + tanh_ap(c[mt][nt][3] + bia[nt][1]);
        }
    #pragma unroll
    for (int nt = 0; nt < 4; nt++)
        #pragma unroll
        for (int u = 0; u < 2; u++){
            float s = csum[nt][u];
            s += __shfl_xor_sync(0xffffffffu, s, 4);
            s += __shfl_xor_sync(0xffffffffu, s, 8);
            s += __shfl_xor_sync(0xffffffffu, s, 16);
            csum[nt][u] = s;
        }
    float* red = smem;
    if ((lane >> 2) == 0){
        #pragma unroll
        for (int nt = 0; nt < 4; nt++){
            int col = wn0 + (nt<<3) + ((lane&3)<<1);
            red[(warp&1)*128 + col]     = csum[nt][0];
            red[(warp&1)*128 + col + 1] = csum[nt][1];
        }
    }
    __syncthreads();
    if (tid < 128) Og[n0 + tid] = red[tid] + red[128 + tid];
}

// ---------------------------------------------------------------------------
__global__ void k_combine(float* __restrict__ out)
{
    const int idx = blockIdx.x * 256 + threadIdx.x;
    const int b = idx >> 9, h = idx & 511;
    float s = 0.f;
    #pragma unroll
    for (int w = 0; w < 2; w++)
        #pragma unroll
        for (int mb = 0; mb < 4; mb++)
            s += g_part[(size_t)((((w*NB) + b)<<2) + mb)*LD + h];
    out[idx] = s * (0.5f / 512.0f);
}

// ---------------------------------------------------------------------------
extern "C" void kernel_launch(void* const* d_in, const int* in_sizes, int n_in,
                              void* d_out, int out_size)
{
    (void)in_sizes; (void)n_in; (void)out_size;
    const float* I    = (const float*)d_in[0];
    const float* J    = (const float*)d_in[1];
    const float* W    = (const float*)d_in[2];
    const float* bias = (const float*)d_in[3];
    float* out = (float*)d_out;

    cudaFuncSetAttribute(k_scores, cudaFuncAttributeMaxDynamicSharedMemorySize, 4*TILE_B);
    cudaFuncSetAttribute(k_wjwi,   cudaFuncAttributeMaxDynamicSharedMemorySize, 4*TILE_B);
    cudaFuncSetAttribute(k_agg,    cudaFuncAttributeMaxDynamicSharedMemorySize, 6*TILE_B);

    k_T      <<<dim3(8,8,NB), 256>>>(J, 0);
    k_T      <<<dim3(8,8,NB), 256>>>(I, 1);
    k_T      <<<dim3(8,8,1),  256>>>(W, 2);
    k_scores <<<dim3(4,4,NB),   256, 4*TILE_B>>>(I, J);
    k_finish <<<2*NBLD/256, 256>>>();
    k_wjwi   <<<dim3(4,4,2*NB), 256, 4*TILE_B>>>();
    k_agg    <<<dim3(16,NB,2),  256, 6*TILE_B>>>(I, J, bias);
    k_combine<<<64, 256>>>(out);
}

// round 6
// speedup vs baseline: 4.7449x; 1.2238x over previous
#include <cuda_runtime.h>
#include <math.h>

#define LD 512
#define NB 32
#define NBLD (NB*LD)
#define TILE_B 16384          // bytes per 128x32 fp32 tile
#define S2 (2*TILE_B)         // bytes per pipeline stage (2 tiles)

// ------------------------- scratch (device globals) -------------------------
__device__ float g_S [(size_t)NB*LD*LD];   // E_row = exp(S - prm_tile)
__device__ float g_ST[(size_t)NB*LD*LD];   // E_col = exp(S^T - pcm_tile)
__device__ float g_wj[(size_t)NB*LD*LD];   // D_i = tf32(|i - wj|)
__device__ float g_wi[(size_t)NB*LD*LD];   // D_j = tf32(|j - wi|)
__device__ float g_jT[(size_t)NB*LD*LD];   // tf32-rounded J^T
__device__ float g_iT[(size_t)NB*LD*LD];   // tf32-rounded I^T
__device__ float g_wT[(size_t)LD*LD];      // tf32-rounded W^T
__device__ float g_prm[NB*4*LD], g_prs[NB*4*LD];
__device__ float g_pcm[NB*4*LD], g_pcs[NB*4*LD];
__device__ float g_rscl[NB*4*LD], g_cscl[NB*4*LD];  // exp(pm_t - M)/Z per k-tile
__device__ float g_part[2*NB*4*LD];

// ------------------------- helpers ------------------------------------------
__device__ __forceinline__ unsigned f2tf(float x){
    unsigned r; asm("cvt.rna.tf32.f32 %0, %1;" : "=r"(r) : "f"(x)); return r;
}
__device__ __forceinline__ float tanh_ap(float x){
    float r; asm("tanh.approx.f32 %0, %1;" : "=f"(r) : "f"(x)); return r;
}
__device__ __forceinline__ void mma8(float* c, unsigned a0,unsigned a1,unsigned a2,unsigned a3,
                                     unsigned b0,unsigned b1){
    asm volatile("mma.sync.aligned.m16n8k8.row.col.f32.tf32.tf32.f32 "
        "{%0,%1,%2,%3}, {%4,%5,%6,%7}, {%8,%9}, {%0,%1,%2,%3};"
        : "+f"(c[0]),"+f"(c[1]),"+f"(c[2]),"+f"(c[3])
        : "r"(a0),"r"(a1),"r"(a2),"r"(a3),"r"(b0),"r"(b1));
}
__device__ __forceinline__ void ldmx4(unsigned* r, unsigned addr){
    asm volatile("ldmatrix.sync.aligned.m8n8.x4.shared.b16 {%0,%1,%2,%3}, [%4];"
        : "=r"(r[0]),"=r"(r[1]),"=r"(r[2]),"=r"(r[3]) : "r"(addr));
}
__device__ __forceinline__ void cpasync16(unsigned saddr, const float* g){
    asm volatile("cp.async.cg.shared.global [%0], [%1], 16;" :: "r"(saddr), "l"(g));
}
__device__ __forceinline__ void cpcommit(){ asm volatile("cp.async.commit_group;"); }
template<int N> __device__ __forceinline__ void cpwait(){
    asm volatile("cp.async.wait_group %0;" :: "n"(N));
}
// stage one 128x32 tile; 16B group g swizzled by g ^ (row & 7)
__device__ __forceinline__ void stage_cp(unsigned sbase, const float* g, int tid){
    #pragma unroll
    for (int q = 0; q < 4; q++){
        int idx = tid + (q << 8);
        int r = idx >> 3, gs = idx & 7;
        cpasync16(sbase + (unsigned)(((r << 5) + ((gs ^ (r & 7)) << 2)) << 2),
                  g + (size_t)r * LD + (gs << 2));
    }
}
// base (ks=0) fragment offsets; per-ks address = (base+off) ^ (ks<<5)
__device__ __forceinline__ unsigned a_off(int row0, int lane){
    int sub = lane >> 3;
    int r = row0 + (lane & 7) + ((sub & 1) << 3);
    int g = (sub >> 1) ^ (r & 7);
    return (unsigned)(((r << 5) + (g << 2)) << 2);
}
__device__ __forceinline__ unsigned b_off(int n0, int lane){
    int sub = lane >> 3;
    int n = n0 + (lane & 7) + ((sub >> 1) << 3);
    int g = (sub & 1) ^ (n & 7);
    return (unsigned)(((n << 5) + (g << 2)) << 2);
}

// ---------------------------------------------------------------------------
// k_T: 512x512 transpose (J, I batched; W once), outputs tf32-rounded.
// ---------------------------------------------------------------------------
__global__ __launch_bounds__(256) void k_T(const float* __restrict__ Jg,
                                           const float* __restrict__ Ig,
                                           const float* __restrict__ Wg)
{
    __shared__ float s[64][65];
    const int z = blockIdx.z;
    const int which = (z >= 64) ? 2 : (z >= 32 ? 1 : 0);
    const int b = (which == 0) ? z : (which == 1 ? z - 32 : 0);
    const float* sp = (which == 0 ? Jg : which == 1 ? Ig : Wg) + (size_t)b*LD*LD;
    float* dst = (which == 0 ? g_jT : which == 1 ? g_iT : g_wT) + (size_t)b*LD*LD;
    const int r0 = blockIdx.y*64, c0 = blockIdx.x*64;
    const int tid = threadIdx.x;
    const int tr = tid >> 4, tc = (tid & 15) << 2;
    #pragma unroll
    for (int rr = 0; rr < 4; rr++){
        int r = tr + (rr << 4);
        float4 v = *(const float4*)&sp[(size_t)(r0 + r)*LD + c0 + tc];
        s[tc+0][r] = v.x; s[tc+1][r] = v.y; s[tc+2][r] = v.z; s[tc+3][r] = v.w;
    }
    __syncthreads();
    #pragma unroll
    for (int rr = 0; rr < 4; rr++){
        int r = tr + (rr << 4);
        float4 w;
        w.x = __uint_as_float(f2tf(s[r][tc]));
        w.y = __uint_as_float(f2tf(s[r][tc+1]));
        w.z = __uint_as_float(f2tf(s[r][tc+2]));
        w.w = __uint_as_float(f2tf(s[r][tc+3]));
        *(float4*)&dst[(size_t)(c0 + r)*LD + r0 + tc] = w;
    }
}

// ---------------------------------------------------------------------------
// k_scores: S = I @ J^T (tf32). Stores E_row/E_col (exp-ed vs per-tile max)
// and per-tile softmax partials. 3-stage cp.async, XOR-reduced addresses.
// ---------------------------------------------------------------------------
__global__ __launch_bounds__(256,2) void k_scores(const float* __restrict__ I,
                                                  const float* __restrict__ J)
{
    extern __shared__ float smem_raw[];
    unsigned su0 = (unsigned)__cvta_generic_to_shared(smem_raw);
    unsigned su = (su0 + 127u) & ~127u;
    float* smem = smem_raw + ((su - su0) >> 2);
    const int b = blockIdx.z, m0 = blockIdx.y*128, n0 = blockIdx.x*128;
    const float* A = I + (size_t)b*LD*LD + (size_t)m0*LD;
    const float* B = J + (size_t)b*LD*LD + (size_t)n0*LD;
    float* C  = g_S  + (size_t)b*LD*LD;
    float* CT = g_ST + (size_t)b*LD*LD;
    const int tid = threadIdx.x, lane = tid & 31, warp = tid >> 5;
    const int wm0 = (warp & 1) << 6, wn0 = (warp >> 1) << 5;
    unsigned aoff[4], boff[2];
    #pragma unroll
    for (int mt = 0; mt < 4; mt++) aoff[mt] = a_off(wm0 + (mt<<4), lane);
    #pragma unroll
    for (int p = 0; p < 2; p++) boff[p] = TILE_B + b_off(wn0 + (p<<4), lane);
    float c[4][4][4] = {};

    stage_cp(su,              A,      tid); stage_cp(su + TILE_B,          B,      tid); cpcommit();
    stage_cp(su + S2,         A + 32, tid); stage_cp(su + S2 + TILE_B,     B + 32, tid); cpcommit();
    int st = 0, pf = 2;
    for (int ch = 0; ch < 16; ch++){
        if (ch < 14){
            unsigned pb = su + pf*S2;
            stage_cp(pb,          A + (ch+2)*32, tid);
            stage_cp(pb + TILE_B, B + (ch+2)*32, tid);
        }
        cpcommit(); cpwait<2>(); __syncthreads();
        unsigned sb = su + st*S2;
        unsigned ab[4], bb[2];
        #pragma unroll
        for (int mt = 0; mt < 4; mt++) ab[mt] = sb + aoff[mt];
        #pragma unroll
        for (int p = 0; p < 2; p++) bb[p] = sb + boff[p];
        #pragma unroll
        for (int ks = 0; ks < 4; ks++){
            unsigned xr = (unsigned)(ks << 5);
            unsigned braw[2][4];
            ldmx4(braw[0], bb[0] ^ xr);
            ldmx4(braw[1], bb[1] ^ xr);
            #pragma unroll
            for (int p = 0; p < 2; p++)
                #pragma unroll
                for (int z = 0; z < 4; z++)
                    braw[p][z] = f2tf(__uint_as_float(braw[p][z]));
            #pragma unroll
            for (int mt = 0; mt < 4; mt++){
                unsigned af[4];
                ldmx4(af, ab[mt] ^ xr);
                #pragma unroll
                for (int z = 0; z < 4; z++) af[z] = f2tf(__uint_as_float(af[z]));
                #pragma unroll
                for (int nt = 0; nt < 4; nt++){
                    int p = nt >> 1, q = (nt & 1) << 1;
                    mma8(c[mt][nt], af[0],af[1],af[2],af[3], braw[p][q], braw[p][q+1]);
                }
            }
        }
        __syncthreads();
        st = (st==2)?0:st+1; pf = (pf==2)?0:pf+1;
    }

    // --- epilogue A: row-softmax partials over this CTA's 128 columns, then
    //     store E_row = exp(c - M_tile[row]).
    {
        float* prm = smem;          // [4][128]
        float* prs = smem + 512;    // [4][128]
        float* Mrow = smem + 1024;  // [128]
        const int wn_idx = warp >> 1;
        #pragma unroll
        for (int mt = 0; mt < 4; mt++){
            float mx1 = -1e30f, mx2 = -1e30f;
            #pragma unroll
            for (int nt = 0; nt < 4; nt++){
                mx1 = fmaxf(mx1, fmaxf(c[mt][nt][0], c[mt][nt][1]));
                mx2 = fmaxf(mx2, fmaxf(c[mt][nt][2], c[mt][nt][3]));
            }
            #pragma unroll
            for (int o = 1; o <= 2; o <<= 1){
                mx1 = fmaxf(mx1, __shfl_xor_sync(0xffffffffu, mx1, o));
                mx2 = fmaxf(mx2, __shfl_xor_sync(0xffffffffu, mx2, o));
            }
            float s1 = 0.f, s2 = 0.f;
            #pragma unroll
            for (int nt = 0; nt < 4; nt++){
                s1 += __expf(c[mt][nt][0]-mx1) + __expf(c[mt][nt][1]-mx1);
                s2 += __expf(c[mt][nt][2]-mx2) + __expf(c[mt][nt][3]-mx2);
            }
            #pragma unroll
            for (int o = 1; o <= 2; o <<= 1){
                s1 += __shfl_xor_sync(0xffffffffu, s1, o);
                s2 += __shfl_xor_sync(0xffffffffu, s2, o);
            }
            if ((lane & 3) == 0){
                int r1 = wm0 + (mt<<4) + (lane>>2);
                prm[wn_idx*128 + r1]     = mx1; prs[wn_idx*128 + r1]     = s1;
                prm[wn_idx*128 + r1 + 8] = mx2; prs[wn_idx*128 + r1 + 8] = s2;
            }
        }
        __syncthreads();
        if (tid < 128){
            float M = -1e30f;
            #pragma unroll
            for (int w = 0; w < 4; w++) M = fmaxf(M, prm[w*128 + tid]);
            float S = 0.f;
            #pragma unroll
            for (int w = 0; w < 4; w++) S += prs[w*128 + tid] * __expf(prm[w*128 + tid] - M);
            int gi = (b*4 + blockIdx.x)*LD + m0 + tid;
            g_prm[gi] = M; g_prs[gi] = S;
            Mrow[tid] = M;
        }
        __syncthreads();
        #pragma unroll
        for (int mt = 0; mt < 4; mt++){
            int r1 = wm0 + (mt<<4) + (lane>>2);
            float M1 = Mrow[r1], M2 = Mrow[r1 + 8];
            int row = m0 + r1;
            #pragma unroll
            for (int nt = 0; nt < 4; nt++){
                int col = n0 + wn0 + (nt<<3) + ((lane&3)<<1);
                *(float2*)&C[(size_t)row*LD + col] =
                    make_float2(__expf(c[mt][nt][0]-M1), __expf(c[mt][nt][1]-M1));
                *(float2*)&C[(size_t)(row+8)*LD + col] =
                    make_float2(__expf(c[mt][nt][2]-M2), __expf(c[mt][nt][3]-M2));
            }
        }
    }

    // --- epilogue B: E_col store via smem transpose + col-softmax partials ---
    const int wh = wn0 >> 6;
    const int mtile4 = (b*4 + blockIdx.y)*LD;
    for (int h = 0; h < 2; h++){
        __syncthreads();
        if (wh == h){
            #pragma unroll
            for (int mt = 0; mt < 4; mt++){
                int rw = wm0 + (mt<<4) + (lane>>2);
                #pragma unroll
                for (int nt = 0; nt < 4; nt++){
                    int cl = wn0 - (h<<6) + (nt<<3) + ((lane&3)<<1);
                    smem[cl*132 + rw]       = c[mt][nt][0];
                    smem[(cl+1)*132 + rw]   = c[mt][nt][1];
                    smem[cl*132 + rw + 8]   = c[mt][nt][2];
                    smem[(cl+1)*132 + rw+8] = c[mt][nt][3];
                }
            }
        }
        __syncthreads();
        #pragma unroll
        for (int w2 = 0; w2 < 8; w2++){
            int orow = warp + (w2 << 3);
            float4 v = *(float4*)&smem[orow*132 + (lane<<2)];
            float mx = fmaxf(fmaxf(v.x, v.y), fmaxf(v.z, v.w));
            #pragma unroll
            for (int o = 16; o; o >>= 1) mx = fmaxf(mx, __shfl_xor_sync(0xffffffffu, mx, o));
            float4 e;
            e.x = __expf(v.x-mx); e.y = __expf(v.y-mx);
            e.z = __expf(v.z-mx); e.w = __expf(v.w-mx);
            *(float4*)&CT[(size_t)(n0 + (h<<6) + orow)*LD + m0 + (lane<<2)] = e;
            float s = e.x + e.y + e.z + e.w;
            #pragma unroll
            for (int o = 16; o; o >>= 1) s += __shfl_xor_sync(0xffffffffu, s, o);
            if (lane == 0){
                int gi = mtile4 + n0 + (h<<6) + orow;
                g_pcm[gi] = mx; g_pcs[gi] = s;
            }
        }
    }
}

// ---------------------------------------------------------------------------
// k_finish: per-row global stats -> per-tile rescale factors exp(pm-M)/Z.
// ---------------------------------------------------------------------------
__global__ __launch_bounds__(256) void k_finish()
{
    const int idx = blockIdx.x * 256 + threadIdx.x;    // [0, 2*NBLD)
    const bool cs = idx >= NBLD;
    const int r = cs ? idx - NBLD : idx;
    const int base = ((r >> 9) << 2)*LD + (r & 511);
    const float* PM = (cs ? g_pcm : g_prm) + base;
    const float* PS = (cs ? g_pcs : g_prs) + base;
    float pm[4];
    #pragma unroll
    for (int t = 0; t < 4; t++) pm[t] = PM[t*LD];
    float M = fmaxf(fmaxf(pm[0], pm[1]), fmaxf(pm[2], pm[3]));
    float S = 0.f;
    #pragma unroll
    for (int t = 0; t < 4; t++) S += PS[t*LD] * __expf(pm[t] - M);
    float inv = 1.0f / S;
    float* OUT = (cs ? g_cscl : g_rscl) + base;
    #pragma unroll
    for (int t = 0; t < 4; t++) OUT[t*LD] = __expf(pm[t] - M) * inv;
}

// ---------------------------------------------------------------------------
// k_wjwi: which=0: wj = P_row @ J (A=E_row*scl, B=jT); which=1 symmetric.
// Epilogue stores D = tf32(|x - acc|) (x = I or J row-matched).
// ---------------------------------------------------------------------------
__global__ __launch_bounds__(256,2) void k_wjwi(const float* __restrict__ Ig,
                                                const float* __restrict__ Jg)
{
    extern __shared__ float smem_raw[];
    unsigned su0 = (unsigned)__cvta_generic_to_shared(smem_raw);
    unsigned su = (su0 + 127u) & ~127u;
    const int z = blockIdx.z, b = z >> 1, which = z & 1;
    const int m0 = blockIdx.y*128, n0 = blockIdx.x*128;
    const float* A  = (which ? g_ST : g_S ) + (size_t)b*LD*LD + (size_t)m0*LD;
    const float* B  = (which ? g_iT : g_jT) + (size_t)b*LD*LD + (size_t)n0*LD;
    float*       C  = (which ? g_wi : g_wj) + (size_t)b*LD*LD;
    const float* X  = (which ? Jg : Ig)     + (size_t)b*LD*LD;
    const float* SC = (which ? g_cscl : g_rscl) + b*4*LD + m0;
    const int tid = threadIdx.x, lane = tid & 31, warp = tid >> 5;
    const int wm0 = (warp & 3) << 5, wn0 = (warp >> 2) << 6;
    unsigned aoff[2], boff[4];
    #pragma unroll
    for (int mt = 0; mt < 2; mt++) aoff[mt] = a_off(wm0 + (mt<<4), lane);
    #pragma unroll
    for (int p = 0; p < 4; p++) boff[p] = TILE_B + b_off(wn0 + (p<<4), lane);
    float scl[4][2][2];
    #pragma unroll
    for (int t = 0; t < 4; t++)
        #pragma unroll
        for (int mt = 0; mt < 2; mt++)
            #pragma unroll
            for (int u = 0; u < 2; u++)
                scl[t][mt][u] = SC[t*LD + wm0 + (mt<<4) + (lane>>2) + (u<<3)];
    float c[2][8][4] = {};

    stage_cp(su,          A,      tid); stage_cp(su + TILE_B,      B,      tid); cpcommit();
    stage_cp(su + S2,     A + 32, tid); stage_cp(su + S2 + TILE_B, B + 32, tid); cpcommit();
    int st = 0, pf = 2;
    #pragma unroll
    for (int t = 0; t < 4; t++){
        #pragma unroll 1
        for (int cc = 0; cc < 4; cc++){
            const int ch = (t<<2) + cc;
            if (ch < 14){
                unsigned pb = su + pf*S2;
                stage_cp(pb,          A + (ch+2)*32, tid);
                stage_cp(pb + TILE_B, B + (ch+2)*32, tid);
            }
            cpcommit(); cpwait<2>(); __syncthreads();
            unsigned sb = su + st*S2;
            unsigned ab[2], bb[4];
            #pragma unroll
            for (int mt = 0; mt < 2; mt++) ab[mt] = sb + aoff[mt];
            #pragma unroll
            for (int p = 0; p < 4; p++) bb[p] = sb + boff[p];
            #pragma unroll
            for (int ks = 0; ks < 4; ks++){
                unsigned xr = (unsigned)(ks << 5);
                unsigned braw[4][4];
                #pragma unroll
                for (int p = 0; p < 4; p++) ldmx4(braw[p], bb[p] ^ xr);
                #pragma unroll
                for (int mt = 0; mt < 2; mt++){
                    unsigned ar[4], af[4];
                    ldmx4(ar, ab[mt] ^ xr);
                    #pragma unroll
                    for (int zz = 0; zz < 4; zz++)
                        af[zz] = f2tf(__uint_as_float(ar[zz]) * scl[t][mt][zz&1]);
                    #pragma unroll
                    for (int nt = 0; nt < 8; nt++){
                        int p = nt >> 1, q = (nt & 1) << 1;
                        mma8(c[mt][nt], af[0],af[1],af[2],af[3], braw[p][q], braw[p][q+1]);
                    }
                }
            }
            __syncthreads();
            st = (st==2)?0:st+1; pf = (pf==2)?0:pf+1;
        }
    }
    // epilogue: D = tf32(|x - acc|)
    #pragma unroll
    for (int mt = 0; mt < 2; mt++){
        int row = m0 + wm0 + (mt<<4) + (lane>>2);
        #pragma unroll
        for (int nt = 0; nt < 8; nt++){
            int col = n0 + wn0 + (nt<<3) + ((lane&3)<<1);
            float2 x1 = *(const float2*)&X[(size_t)row*LD + col];
            float2 x2 = *(const float2*)&X[(size_t)(row+8)*LD + col];
            float2 d1, d2;
            d1.x = __uint_as_float(f2tf(fabsf(x1.x - c[mt][nt][0])));
            d1.y = __uint_as_float(f2tf(fabsf(x1.y - c[mt][nt][1])));
            d2.x = __uint_as_float(f2tf(fabsf(x2.x - c[mt][nt][2])));
            d2.y = __uint_as_float(f2tf(fabsf(x2.y - c[mt][nt][3])));
            *(float2*)&C[(size_t)row*LD + col]     = d1;
            *(float2*)&C[(size_t)(row+8)*LD + col] = d2;
        }
    }
}

// ---------------------------------------------------------------------------
// k_agg: partial colsum over 128 rows of tanh(D @ wT + bias). Pure ldmx+mma.
// ---------------------------------------------------------------------------
__global__ __launch_bounds__(256,2) void k_agg(const float* __restrict__ bias)
{
    extern __shared__ float smem_raw[];
    unsigned su0 = (unsigned)__cvta_generic_to_shared(smem_raw);
    unsigned su = (su0 + 127u) & ~127u;
    float* smem = smem_raw + ((su - su0) >> 2);
    const int bx = blockIdx.x, b = blockIdx.y, which = blockIdx.z;
    const int n0 = (bx & 3) << 7, mb = bx >> 2;
    const float* D  = (which ? g_wi : g_wj) + (size_t)b*LD*LD + (size_t)(mb<<7)*LD;
    const float* Bm = g_wT + (size_t)n0*LD;
    float* Og = g_part + (size_t)((((which*NB) + b)<<2) + mb)*LD;
    const int tid = threadIdx.x, lane = tid & 31, warp = tid >> 5;
    const int wm0 = (warp & 1) << 6, wn0 = (warp >> 1) << 5;
    unsigned aoff[4], boff[2];
    #pragma unroll
    for (int mt = 0; mt < 4; mt++) aoff[mt] = a_off(wm0 + (mt<<4), lane);
    #pragma unroll
    for (int p = 0; p < 2; p++) boff[p] = TILE_B + b_off(wn0 + (p<<4), lane);
    float bia[4][2];
    #pragma unroll
    for (int nt = 0; nt < 4; nt++){
        int col = n0 + wn0 + (nt<<3) + ((lane&3)<<1);
        bia[nt][0] = bias[col]; bia[nt][1] = bias[col+1];
    }
    float c[4][4][4] = {};

    stage_cp(su,          D,      tid); stage_cp(su + TILE_B,      Bm,      tid); cpcommit();
    stage_cp(su + S2,     D + 32, tid); stage_cp(su + S2 + TILE_B, Bm + 32, tid); cpcommit();
    int st = 0, pf = 2;
    for (int ch = 0; ch < 16; ch++){
        if (ch < 14){
            unsigned pb = su + pf*S2;
            stage_cp(pb,          D  + (ch+2)*32, tid);
            stage_cp(pb + TILE_B, Bm + (ch+2)*32, tid);
        }
        cpcommit(); cpwait<2>(); __syncthreads();
        unsigned sb = su + st*S2;
        unsigned ab[4], bb[2];
        #pragma unroll
        for (int mt = 0; mt < 4; mt++) ab[mt] = sb + aoff[mt];
        #pragma unroll
        for (int p = 0; p < 2; p++) bb[p] = sb + boff[p];
        #pragma unroll
        for (int ks = 0; ks < 4; ks++){
            unsigned xr = (unsigned)(ks << 5);
            unsigned braw[2][4];
            ldmx4(braw[0], bb[0] ^ xr);
            ldmx4(braw[1], bb[1] ^ xr);
            #pragma unroll
            for (int mt = 0; mt < 4; mt++){
                unsigned af[4];
                ldmx4(af, ab[mt] ^ xr);
                #pragma unroll
                for (int nt = 0; nt < 4; nt++){
                    int p = nt >> 1, q = (nt & 1) << 1;
                    mma8(c[mt][nt], af[0],af[1],af[2],af[3], braw[p][q], braw[p][q+1]);
                }
            }
        }
        __syncthreads();
        st = (st==2)?0:st+1; pf = (pf==2)?0:pf+1;
    }
    float csum[4][2] = {};
    #pragma unroll
    for (int mt = 0; mt < 4; mt++)
        #pragma unroll
        for (int nt = 0; nt < 4; nt++){
            csum[nt][0] += tanh_ap(c[mt][nt][0] + bia[nt][0]) + tanh_ap(c[mt][nt][2] + bia[nt][0]);
            csum[nt][1] += tanh_ap(c[mt][nt][1] + bia[nt][1]) + tanh_ap(c[mt][nt][3] + bia[nt][1]);
        }
    #pragma unroll
    for (int nt = 0; nt < 4; nt++)
        #pragma unroll
        for (int u = 0; u < 2; u++){
            float s = csum[nt][u];
            s += __shfl_xor_sync(0xffffffffu, s, 4);
            s += __shfl_xor_sync(0xffffffffu, s, 8);
            s += __shfl_xor_sync(0xffffffffu, s, 16);
            csum[nt][u] = s;
        }
    float* red = smem;
    if ((lane >> 2) == 0){
        #pragma unroll
        for (int nt = 0; nt < 4; nt++){
            int col = wn0 + (nt<<3) + ((lane&3)<<1);
            red[(warp&1)*128 + col]     = csum[nt][0];
            red[(warp&1)*128 + col + 1] = csum[nt][1];
        }
    }
    __syncthreads();
    if (tid < 128) Og[n0 + tid] = red[tid] + red[128 + tid];
}

// ---------------------------------------------------------------------------
__global__ void k_combine(float* __restrict__ out)
{
    const int idx = blockIdx.x * 256 + threadIdx.x;
    const int b = idx >> 9, h = idx & 511;
    float s = 0.f;
    #pragma unroll
    for (int w = 0; w < 2; w++)
        #pragma unroll
        for (int mb = 0; mb < 4; mb++)
            s += g_part[(size_t)((((w*NB) + b)<<2) + mb)*LD + h];
    out[idx] = s * (0.5f / 512.0f);
}

// ---------------------------------------------------------------------------
extern "C" void kernel_launch(void* const* d_in, const int* in_sizes, int n_in,
                              void* d_out, int out_size)
{
    (void)in_sizes; (void)n_in; (void)out_size;
    const float* I    = (const float*)d_in[0];
    const float* J    = (const float*)d_in[1];
    const float* W    = (const float*)d_in[2];
    const float* bias = (const float*)d_in[3];
    float* out = (float*)d_out;

    const int SM = 3*S2 + 256;   // 3-stage pipeline + alignment slack
    cudaFuncSetAttribute(k_scores, cudaFuncAttributeMaxDynamicSharedMemorySize, SM);
    cudaFuncSetAttribute(k_wjwi,   cudaFuncAttributeMaxDynamicSharedMemorySize, SM);
    cudaFuncSetAttribute(k_agg,    cudaFuncAttributeMaxDynamicSharedMemorySize, SM);

    k_T      <<<dim3(8,8,65), 256>>>(J, I, W);
    k_scores <<<dim3(4,4,NB),   256, SM>>>(I, J);
    k_finish <<<2*NBLD/256, 256>>>();
    k_wjwi   <<<dim3(4,4,2*NB), 256, SM>>>(I, J);
    k_agg    <<<dim3(16,NB,2),  256, SM>>>(bias);
    k_combine<<<64, 256>>>(out);
}

// round 7
// speedup vs baseline: 7.6910x; 1.6209x over previous
#include <cuda_runtime.h>
#include <cuda_fp16.h>
#include <math.h>

#define LD 512
#define NB 32
#define NBLD (NB*LD)
#define TILE_B 16384          // bytes per 128x64 fp16 tile (BK=64)
#define S2 (2*TILE_B)         // bytes per pipeline stage (2 tiles)

// ---------------- scratch (declared as float for 16B-safe alignment) --------
__device__ float g_S_raw [(size_t)NB*LD*LD/2];  // E_row fp16
__device__ float g_ST_raw[(size_t)NB*LD*LD/2];  // E_col fp16
__device__ float g_Di_raw[(size_t)NB*LD*LD/2];  // D_i = |i - wj| fp16
__device__ float g_Dj_raw[(size_t)NB*LD*LD/2];  // D_j = |j - wi| fp16
__device__ float g_ih_raw[(size_t)NB*LD*LD/2];  // I fp16 row-major
__device__ float g_jh_raw[(size_t)NB*LD*LD/2];  // J fp16 row-major
__device__ float g_iT_raw[(size_t)NB*LD*LD/2];  // I^T fp16
__device__ float g_jT_raw[(size_t)NB*LD*LD/2];  // J^T fp16
__device__ float g_wT_raw[(size_t)LD*LD/2];     // W^T fp16
#define g_S  ((__half*)g_S_raw)
#define g_ST ((__half*)g_ST_raw)
#define g_Di ((__half*)g_Di_raw)
#define g_Dj ((__half*)g_Dj_raw)
#define g_ih ((__half*)g_ih_raw)
#define g_jh ((__half*)g_jh_raw)
#define g_iT ((__half*)g_iT_raw)
#define g_jT ((__half*)g_jT_raw)
#define g_wT ((__half*)g_wT_raw)
__device__ float g_prm[NB*4*LD], g_prs[NB*4*LD];
__device__ float g_pcm[NB*4*LD], g_pcs[NB*4*LD];
__device__ float g_rscl[NB*4*LD], g_cscl[NB*4*LD];
__device__ float g_part[2*NB*4*LD];

// ------------------------- helpers ------------------------------------------
__device__ __forceinline__ float tanh_ap(float x){
    float r; asm("tanh.approx.f32 %0, %1;" : "=f"(r) : "f"(x)); return r;
}
__device__ __forceinline__ void mma16(float* c, unsigned a0,unsigned a1,unsigned a2,unsigned a3,
                                      unsigned b0,unsigned b1){
    asm volatile("mma.sync.aligned.m16n8k16.row.col.f32.f16.f16.f32 "
        "{%0,%1,%2,%3}, {%4,%5,%6,%7}, {%8,%9}, {%0,%1,%2,%3};"
        : "+f"(c[0]),"+f"(c[1]),"+f"(c[2]),"+f"(c[3])
        : "r"(a0),"r"(a1),"r"(a2),"r"(a3),"r"(b0),"r"(b1));
}
__device__ __forceinline__ void ldmx4(unsigned* r, unsigned addr){
    asm volatile("ldmatrix.sync.aligned.m8n8.x4.shared.b16 {%0,%1,%2,%3}, [%4];"
        : "=r"(r[0]),"=r"(r[1]),"=r"(r[2]),"=r"(r[3]) : "r"(addr));
}
__device__ __forceinline__ void cpasync16(unsigned saddr, const void* g){
    asm volatile("cp.async.cg.shared.global [%0], [%1], 16;" :: "r"(saddr), "l"(g));
}
__device__ __forceinline__ void cpcommit(){ asm volatile("cp.async.commit_group;"); }
template<int N> __device__ __forceinline__ void cpwait(){
    asm volatile("cp.async.wait_group %0;" :: "n"(N));
}
__device__ __forceinline__ unsigned hmul2u(unsigned a, unsigned b){
    __half2 r = __hmul2(*(__half2*)&a, *(__half2*)&b);
    return *(unsigned*)&r;
}
// stage one 128x64 fp16 tile (16 KB); 16B group gs swizzled by gs ^ (r & 7)
__device__ __forceinline__ void stage_cph(unsigned sbase, const __half* g, int tid){
    #pragma unroll
    for (int q = 0; q < 4; q++){
        int idx = tid + (q << 8);
        int r = idx >> 3, gs = idx & 7;
        cpasync16(sbase + (unsigned)(((r << 5) + ((gs ^ (r & 7)) << 2)) << 2),
                  g + (size_t)r * LD + (gs << 3));
    }
}
// fragment base offsets (bytes), identical byte layout to the fp32 BK=32 case
__device__ __forceinline__ unsigned a_off(int row0, int lane){
    int sub = lane >> 3;
    int r = row0 + (lane & 7) + ((sub & 1) << 3);
    int g = (sub >> 1) ^ (r & 7);
    return (unsigned)(((r << 5) + (g << 2)) << 2);
}
__device__ __forceinline__ unsigned b_off(int n0, int lane){
    int sub = lane >> 3;
    int n = n0 + (lane & 7) + ((sub >> 1) << 3);
    int g = (sub & 1) ^ (n & 7);
    return (unsigned)(((n << 5) + (g << 2)) << 2);
}

// ---------------------------------------------------------------------------
// k_conv: fp32 -> fp16 copies (row-major for I/J) + fp16 transposes (I,J,W).
// ---------------------------------------------------------------------------
__global__ __launch_bounds__(256) void k_conv(const float* __restrict__ Jg,
                                              const float* __restrict__ Ig,
                                              const float* __restrict__ Wg)
{
    __shared__ float s[64][65];
    const int z = blockIdx.z;
    const int which = (z >= 64) ? 2 : (z >= 32 ? 1 : 0);
    const int b = (which == 0) ? z : (which == 1 ? z - 32 : 0);
    const float* sp = (which == 0 ? Jg : which == 1 ? Ig : Wg) + (size_t)b*LD*LD;
    __half* dn = (which == 0 ? g_jh : which == 1 ? g_ih : (__half*)0);
    __half* dt = (which == 0 ? g_jT : which == 1 ? g_iT : g_wT);
    if (dn) dn += (size_t)b*LD*LD;
    dt += (size_t)b*LD*LD;
    const int r0 = blockIdx.y*64, c0 = blockIdx.x*64;
    const int tid = threadIdx.x;
    const int tr = tid >> 4, tc = (tid & 15) << 2;
    #pragma unroll
    for (int rr = 0; rr < 4; rr++){
        int r = tr + (rr << 4);
        float4 v = *(const float4*)&sp[(size_t)(r0 + r)*LD + c0 + tc];
        if (dn){
            __half2* p = (__half2*)&dn[(size_t)(r0 + r)*LD + c0 + tc];
            p[0] = __floats2half2_rn(v.x, v.y);
            p[1] = __floats2half2_rn(v.z, v.w);
        }
        s[tc+0][r] = v.x; s[tc+1][r] = v.y; s[tc+2][r] = v.z; s[tc+3][r] = v.w;
    }
    __syncthreads();
    #pragma unroll
    for (int rr = 0; rr < 4; rr++){
        int r = tr + (rr << 4);
        __half2* p = (__half2*)&dt[(size_t)(c0 + r)*LD + r0 + tc];
        p[0] = __floats2half2_rn(s[r][tc],   s[r][tc+1]);
        p[1] = __floats2half2_rn(s[r][tc+2], s[r][tc+3]);
    }
}

// ---------------------------------------------------------------------------
// k_scores: S = I @ J^T (fp16 mma, fp32 accum). Stores E_row/E_col (fp16)
// + per-tile softmax partials. 3-stage cp.async, BK=64, 8 chunks.
// ---------------------------------------------------------------------------
__global__ __launch_bounds__(256,2) void k_scores()
{
    extern __shared__ float smem_raw[];
    unsigned su0 = (unsigned)__cvta_generic_to_shared(smem_raw);
    unsigned su = (su0 + 127u) & ~127u;
    float* smem = smem_raw + ((su - su0) >> 2);
    const int b = blockIdx.z, m0 = blockIdx.y*128, n0 = blockIdx.x*128;
    const __half* A = g_ih + (size_t)b*LD*LD + (size_t)m0*LD;
    const __half* B = g_jh + (size_t)b*LD*LD + (size_t)n0*LD;
    __half* C  = g_S  + (size_t)b*LD*LD;
    __half* CT = g_ST + (size_t)b*LD*LD;
    const int tid = threadIdx.x, lane = tid & 31, warp = tid >> 5;
    const int wm0 = (warp & 1) << 6, wn0 = (warp >> 1) << 5;
    unsigned aoff[4], boff[2];
    #pragma unroll
    for (int mt = 0; mt < 4; mt++) aoff[mt] = a_off(wm0 + (mt<<4), lane);
    #pragma unroll
    for (int p = 0; p < 2; p++) boff[p] = TILE_B + b_off(wn0 + (p<<4), lane);
    float c[4][4][4] = {};

    stage_cph(su,          A,      tid); stage_cph(su + TILE_B,      B,      tid); cpcommit();
    stage_cph(su + S2,     A + 64, tid); stage_cph(su + S2 + TILE_B, B + 64, tid); cpcommit();
    int st = 0, pf = 2;
    for (int ch = 0; ch < 8; ch++){
        if (ch < 6){
            unsigned pb = su + pf*S2;
            stage_cph(pb,          A + (ch+2)*64, tid);
            stage_cph(pb + TILE_B, B + (ch+2)*64, tid);
        }
        cpcommit(); cpwait<2>(); __syncthreads();
        unsigned sb = su + st*S2;
        unsigned ab[4], bb[2];
        #pragma unroll
        for (int mt = 0; mt < 4; mt++) ab[mt] = sb + aoff[mt];
        #pragma unroll
        for (int p = 0; p < 2; p++) bb[p] = sb + boff[p];
        #pragma unroll
        for (int ks = 0; ks < 4; ks++){
            unsigned xr = (unsigned)(ks << 5);
            unsigned braw[2][4];
            ldmx4(braw[0], bb[0] ^ xr);
            ldmx4(braw[1], bb[1] ^ xr);
            #pragma unroll
            for (int mt = 0; mt < 4; mt++){
                unsigned af[4];
                ldmx4(af, ab[mt] ^ xr);
                #pragma unroll
                for (int nt = 0; nt < 4; nt++){
                    int p = nt >> 1, q = (nt & 1) << 1;
                    mma16(c[mt][nt], af[0],af[1],af[2],af[3], braw[p][q], braw[p][q+1]);
                }
            }
        }
        __syncthreads();
        st = (st==2)?0:st+1; pf = (pf==2)?0:pf+1;
    }

    // --- epilogue A: row-softmax partials + E_row store (fp16) ---
    {
        float* prm = smem;          // [4][128]
        float* prs = smem + 512;    // [4][128]
        float* Mrow = smem + 1024;  // [128]
        const int wn_idx = warp >> 1;
        #pragma unroll
        for (int mt = 0; mt < 4; mt++){
            float mx1 = -1e30f, mx2 = -1e30f;
            #pragma unroll
            for (int nt = 0; nt < 4; nt++){
                mx1 = fmaxf(mx1, fmaxf(c[mt][nt][0], c[mt][nt][1]));
                mx2 = fmaxf(mx2, fmaxf(c[mt][nt][2], c[mt][nt][3]));
            }
            #pragma unroll
            for (int o = 1; o <= 2; o <<= 1){
                mx1 = fmaxf(mx1, __shfl_xor_sync(0xffffffffu, mx1, o));
                mx2 = fmaxf(mx2, __shfl_xor_sync(0xffffffffu, mx2, o));
            }
            float s1 = 0.f, s2 = 0.f;
            #pragma unroll
            for (int nt = 0; nt < 4; nt++){
                s1 += __expf(c[mt][nt][0]-mx1) + __expf(c[mt][nt][1]-mx1);
                s2 += __expf(c[mt][nt][2]-mx2) + __expf(c[mt][nt][3]-mx2);
            }
            #pragma unroll
            for (int o = 1; o <= 2; o <<= 1){
                s1 += __shfl_xor_sync(0xffffffffu, s1, o);
                s2 += __shfl_xor_sync(0xffffffffu, s2, o);
            }
            if ((lane & 3) == 0){
                int r1 = wm0 + (mt<<4) + (lane>>2);
                prm[wn_idx*128 + r1]     = mx1; prs[wn_idx*128 + r1]     = s1;
                prm[wn_idx*128 + r1 + 8] = mx2; prs[wn_idx*128 + r1 + 8] = s2;
            }
        }
        __syncthreads();
        if (tid < 128){
            float M = -1e30f;
            #pragma unroll
            for (int w = 0; w < 4; w++) M = fmaxf(M, prm[w*128 + tid]);
            float S = 0.f;
            #pragma unroll
            for (int w = 0; w < 4; w++) S += prs[w*128 + tid] * __expf(prm[w*128 + tid] - M);
            int gi = (b*4 + blockIdx.x)*LD + m0 + tid;
            g_prm[gi] = M; g_prs[gi] = S;
            Mrow[tid] = M;
        }
        __syncthreads();
        #pragma unroll
        for (int mt = 0; mt < 4; mt++){
            int r1 = wm0 + (mt<<4) + (lane>>2);
            float M1 = Mrow[r1], M2 = Mrow[r1 + 8];
            int row = m0 + r1;
            #pragma unroll
            for (int nt = 0; nt < 4; nt++){
                int col = n0 + wn0 + (nt<<3) + ((lane&3)<<1);
                *(__half2*)&C[(size_t)row*LD + col] =
                    __floats2half2_rn(__expf(c[mt][nt][0]-M1), __expf(c[mt][nt][1]-M1));
                *(__half2*)&C[(size_t)(row+8)*LD + col] =
                    __floats2half2_rn(__expf(c[mt][nt][2]-M2), __expf(c[mt][nt][3]-M2));
            }
        }
    }

    // --- epilogue B: E_col store (fp16) via smem transpose + col partials ---
    const int wh = wn0 >> 6;
    const int mtile4 = (b*4 + blockIdx.y)*LD;
    for (int h = 0; h < 2; h++){
        __syncthreads();
        if (wh == h){
            #pragma unroll
            for (int mt = 0; mt < 4; mt++){
                int rw = wm0 + (mt<<4) + (lane>>2);
                #pragma unroll
                for (int nt = 0; nt < 4; nt++){
                    int cl = wn0 - (h<<6) + (nt<<3) + ((lane&3)<<1);
                    smem[cl*132 + rw]       = c[mt][nt][0];
                    smem[(cl+1)*132 + rw]   = c[mt][nt][1];
                    smem[cl*132 + rw + 8]   = c[mt][nt][2];
                    smem[(cl+1)*132 + rw+8] = c[mt][nt][3];
                }
            }
        }
        __syncthreads();
        #pragma unroll
        for (int w2 = 0; w2 < 8; w2++){
            int orow = warp + (w2 << 3);
            float4 v = *(float4*)&smem[orow*132 + (lane<<2)];
            float mx = fmaxf(fmaxf(v.x, v.y), fmaxf(v.z, v.w));
            #pragma unroll
            for (int o = 16; o; o >>= 1) mx = fmaxf(mx, __shfl_xor_sync(0xffffffffu, mx, o));
            float4 e;
            e.x = __expf(v.x-mx); e.y = __expf(v.y-mx);
            e.z = __expf(v.z-mx); e.w = __expf(v.w-mx);
            __half2 h0 = __floats2half2_rn(e.x, e.y);
            __half2 h1 = __floats2half2_rn(e.z, e.w);
            __half2* dst = (__half2*)&CT[(size_t)(n0 + (h<<6) + orow)*LD + m0 + (lane<<2)];
            dst[0] = h0; dst[1] = h1;
            float s = e.x + e.y + e.z + e.w;
            #pragma unroll
            for (int o = 16; o; o >>= 1) s += __shfl_xor_sync(0xffffffffu, s, o);
            if (lane == 0){
                int gi = mtile4 + n0 + (h<<6) + orow;
                g_pcm[gi] = mx; g_pcs[gi] = s;
            }
        }
    }
}

// ---------------------------------------------------------------------------
// k_finish: per-row global stats -> per-k-tile rescale factors exp(pm-M)/Z.
// ---------------------------------------------------------------------------
__global__ __launch_bounds__(256) void k_finish()
{
    const int idx = blockIdx.x * 256 + threadIdx.x;
    const bool cs = idx >= NBLD;
    const int r = cs ? idx - NBLD : idx;
    const int base = ((r >> 9) << 2)*LD + (r & 511);
    const float* PM = (cs ? g_pcm : g_prm) + base;
    const float* PS = (cs ? g_pcs : g_prs) + base;
    float pm[4];
    #pragma unroll
    for (int t = 0; t < 4; t++) pm[t] = PM[t*LD];
    float M = fmaxf(fmaxf(pm[0], pm[1]), fmaxf(pm[2], pm[3]));
    float S = 0.f;
    #pragma unroll
    for (int t = 0; t < 4; t++) S += PS[t*LD] * __expf(pm[t] - M);
    float inv = 1.0f / S;
    float* OUT = (cs ? g_cscl : g_rscl) + base;
    #pragma unroll
    for (int t = 0; t < 4; t++) OUT[t*LD] = __expf(pm[t] - M) * inv;
}

// ---------------------------------------------------------------------------
// k_wjwi: which=0: wj = P_row @ J (A=E_row*scl fp16, B=jT fp16); which=1 sym.
// Epilogue stores D = fp16(|x - acc|) with x from fp16 copies.
// ---------------------------------------------------------------------------
__global__ __launch_bounds__(256,2) void k_wjwi()
{
    extern __shared__ float smem_raw[];
    unsigned su0 = (unsigned)__cvta_generic_to_shared(smem_raw);
    unsigned su = (su0 + 127u) & ~127u;
    const int z = blockIdx.z, b = z >> 1, which = z & 1;
    const int m0 = blockIdx.y*128, n0 = blockIdx.x*128;
    const __half* A  = (which ? g_ST : g_S ) + (size_t)b*LD*LD + (size_t)m0*LD;
    const __half* B  = (which ? g_iT : g_jT) + (size_t)b*LD*LD + (size_t)n0*LD;
    __half*       C  = (which ? g_Dj : g_Di) + (size_t)b*LD*LD;
    const __half* X  = (which ? g_jh : g_ih) + (size_t)b*LD*LD;
    const float* SC = (which ? g_cscl : g_rscl) + b*4*LD + m0;
    const int tid = threadIdx.x, lane = tid & 31, warp = tid >> 5;
    const int wm0 = (warp & 3) << 5, wn0 = (warp >> 2) << 6;
    unsigned aoff[2], boff[4];
    #pragma unroll
    for (int mt = 0; mt < 2; mt++) aoff[mt] = a_off(wm0 + (mt<<4), lane);
    #pragma unroll
    for (int p = 0; p < 4; p++) boff[p] = TILE_B + b_off(wn0 + (p<<4), lane);
    unsigned hscl[4][2][2];
    #pragma unroll
    for (int t = 0; t < 4; t++)
        #pragma unroll
        for (int mt = 0; mt < 2; mt++)
            #pragma unroll
            for (int u = 0; u < 2; u++){
                __half2 h = __float2half2_rn(SC[t*LD + wm0 + (mt<<4) + (lane>>2) + (u<<3)]);
                hscl[t][mt][u] = *(unsigned*)&h;
            }
    float c[2][8][4] = {};

    stage_cph(su,          A,      tid); stage_cph(su + TILE_B,      B,      tid); cpcommit();
    stage_cph(su + S2,     A + 64, tid); stage_cph(su + S2 + TILE_B, B + 64, tid); cpcommit();
    int st = 0, pf = 2;
    #pragma unroll 1
    for (int ch = 0; ch < 8; ch++){
        const int t = ch >> 1;
        if (ch < 6){
            unsigned pb = su + pf*S2;
            stage_cph(pb,          A + (ch+2)*64, tid);
            stage_cph(pb + TILE_B, B + (ch+2)*64, tid);
        }
        cpcommit(); cpwait<2>(); __syncthreads();
        unsigned sb = su + st*S2;
        unsigned ab[2], bb[4];
        #pragma unroll
        for (int mt = 0; mt < 2; mt++) ab[mt] = sb + aoff[mt];
        #pragma unroll
        for (int p = 0; p < 4; p++) bb[p] = sb + boff[p];
        #pragma unroll
        for (int ks = 0; ks < 4; ks++){
            unsigned xr = (unsigned)(ks << 5);
            unsigned braw[4][4];
            #pragma unroll
            for (int p = 0; p < 4; p++) ldmx4(braw[p], bb[p] ^ xr);
            #pragma unroll
            for (int mt = 0; mt < 2; mt++){
                unsigned ar[4], af[4];
                ldmx4(ar, ab[mt] ^ xr);
                #pragma unroll
                for (int zz = 0; zz < 4; zz++)
                    af[zz] = hmul2u(ar[zz], hscl[t][mt][zz&1]);
                #pragma unroll
                for (int nt = 0; nt < 8; nt++){
                    int p = nt >> 1, q = (nt & 1) << 1;
                    mma16(c[mt][nt], af[0],af[1],af[2],af[3], braw[p][q], braw[p][q+1]);
                }
            }
        }
        __syncthreads();
        st = (st==2)?0:st+1; pf = (pf==2)?0:pf+1;
    }
    // epilogue: D = fp16(|x - acc|)
    #pragma unroll
    for (int mt = 0; mt < 2; mt++){
        int row = m0 + wm0 + (mt<<4) + (lane>>2);
        #pragma unroll
        for (int nt = 0; nt < 8; nt++){
            int col = n0 + wn0 + (nt<<3) + ((lane&3)<<1);
            float2 x1 = __half22float2(*(const __half2*)&X[(size_t)row*LD + col]);
            float2 x2 = __half22float2(*(const __half2*)&X[(size_t)(row+8)*LD + col]);
            *(__half2*)&C[(size_t)row*LD + col] =
                __floats2half2_rn(fabsf(x1.x - c[mt][nt][0]), fabsf(x1.y - c[mt][nt][1]));
            *(__half2*)&C[(size_t)(row+8)*LD + col] =
                __floats2half2_rn(fabsf(x2.x - c[mt][nt][2]), fabsf(x2.y - c[mt][nt][3]));
        }
    }
}

// ---------------------------------------------------------------------------
// k_agg: partial colsum over 128 rows of tanh(D @ wT + bias). Pure ldmx+mma.
// ---------------------------------------------------------------------------
__global__ __launch_bounds__(256,2) void k_agg(const float* __restrict__ bias)
{
    extern __shared__ float smem_raw[];
    unsigned su0 = (unsigned)__cvta_generic_to_shared(smem_raw);
    unsigned su = (su0 + 127u) & ~127u;
    float* smem = smem_raw + ((su - su0) >> 2);
    const int bx = blockIdx.x, b = blockIdx.y, which = blockIdx.z;
    const int n0 = (bx & 3) << 7, mb = bx >> 2;
    const __half* D  = (which ? g_Dj : g_Di) + (size_t)b*LD*LD + (size_t)(mb<<7)*LD;
    const __half* Bm = g_wT + (size_t)n0*LD;
    float* Og = g_part + (size_t)((((which*NB) + b)<<2) + mb)*LD;
    const int tid = threadIdx.x, lane = tid & 31, warp = tid >> 5;
    const int wm0 = (warp & 1) << 6, wn0 = (warp >> 1) << 5;
    unsigned aoff[4], boff[2];
    #pragma unroll
    for (int mt = 0; mt < 4; mt++) aoff[mt] = a_off(wm0 + (mt<<4), lane);
    #pragma unroll
    for (int p = 0; p < 2; p++) boff[p] = TILE_B + b_off(wn0 + (p<<4), lane);
    float bia[4][2];
    #pragma unroll
    for (int nt = 0; nt < 4; nt++){
        int col = n0 + wn0 + (nt<<3) + ((lane&3)<<1);
        bia[nt][0] = bias[col]; bia[nt][1] = bias[col+1];
    }
    float c[4][4][4] = {};

    stage_cph(su,          D,      tid); stage_cph(su + TILE_B,      Bm,      tid); cpcommit();
    stage_cph(su + S2,     D + 64, tid); stage_cph(su + S2 + TILE_B, Bm + 64, tid); cpcommit();
    int st = 0, pf = 2;
    for (int ch = 0; ch < 8; ch++){
        if (ch < 6){
            unsigned pb = su + pf*S2;
            stage_cph(pb,          D  + (ch+2)*64, tid);
            stage_cph(pb + TILE_B, Bm + (ch+2)*64, tid);
        }
        cpcommit(); cpwait<2>(); __syncthreads();
        unsigned sb = su + st*S2;
        unsigned ab[4], bb[2];
        #pragma unroll
        for (int mt = 0; mt < 4; mt++) ab[mt] = sb + aoff[mt];
        #pragma unroll
        for (int p = 0; p < 2; p++) bb[p] = sb + boff[p];
        #pragma unroll
        for (int ks = 0; ks < 4; ks++){
            unsigned xr = (unsigned)(ks << 5);
            unsigned braw[2][4];
            ldmx4(braw[0], bb[0] ^ xr);
            ldmx4(braw[1], bb[1] ^ xr);
            #pragma unroll
            for (int mt = 0; mt < 4; mt++){
                unsigned af[4];
                ldmx4(af, ab[mt] ^ xr);
                #pragma unroll
                for (int nt = 0; nt < 4; nt++){
                    int p = nt >> 1, q = (nt & 1) << 1;
                    mma16(c[mt][nt], af[0],af[1],af[2],af[3], braw[p][q], braw[p][q+1]);
                }
            }
        }
        __syncthreads();
        st = (st==2)?0:st+1; pf = (pf==2)?0:pf+1;
    }
    float csum[4][2] = {};
    #pragma unroll
    for (int mt = 0; mt < 4; mt++)
        #pragma unroll
        for (int nt = 0; nt < 4; nt++){
            csum[nt][0] += tanh_ap(c[mt][nt][0] + bia[nt][0]) + tanh_ap(c[mt][nt][2] + bia[nt][0]);
            csum[nt][1] += tanh_ap(c[mt][nt][1] + bia[nt][1]) + tanh_ap(c[mt][nt][3] + bia[nt][1]);
        }
    #pragma unroll
    for (int nt = 0; nt < 4; nt++)
        #pragma unroll
        for (int u = 0; u < 2; u++){
            float s = csum[nt][u];
            s += __shfl_xor_sync(0xffffffffu, s, 4);
            s += __shfl_xor_sync(0xffffffffu, s, 8);
            s += __shfl_xor_sync(0xffffffffu, s, 16);
            csum[nt][u] = s;
        }
    float* red = smem;
    if ((lane >> 2) == 0){
        #pragma unroll
        for (int nt = 0; nt < 4; nt++){
            int col = wn0 + (nt<<3) + ((lane&3)<<1);
            red[(warp&1)*128 + col]     = csum[nt][0];
            red[(warp&1)*128 + col + 1] = csum[nt][1];
        }
    }
    __syncthreads();
    if (tid < 128) Og[n0 + tid] = red[tid] + red[128 + tid];
}

// ---------------------------------------------------------------------------
__global__ void k_combine(float* __restrict__ out)
{
    const int idx = blockIdx.x * 256 + threadIdx.x;
    const int b = idx >> 9, h = idx & 511;
    float s = 0.f;
    #pragma unroll
    for (int w = 0; w < 2; w++)
        #pragma unroll
        for (int mb = 0; mb < 4; mb++)
            s += g_part[(size_t)((((w*NB) + b)<<2) + mb)*LD + h];
    out[idx] = s * (0.5f / 512.0f);
}

// ---------------------------------------------------------------------------
extern "C" void kernel_launch(void* const* d_in, const int* in_sizes, int n_in,
                              void* d_out, int out_size)
{
    (void)in_sizes; (void)n_in; (void)out_size;
    const float* I    = (const float*)d_in[0];
    const float* J    = (const float*)d_in[1];
    const float* W    = (const float*)d_in[2];
    const float* bias = (const float*)d_in[3];
    float* out = (float*)d_out;

    const int SM = 3*S2 + 256;
    cudaFuncSetAttribute(k_scores, cudaFuncAttributeMaxDynamicSharedMemorySize, SM);
    cudaFuncSetAttribute(k_wjwi,   cudaFuncAttributeMaxDynamicSharedMemorySize, SM);
    cudaFuncSetAttribute(k_agg,    cudaFuncAttributeMaxDynamicSharedMemorySize, SM);

    k_conv   <<<dim3(8,8,65), 256>>>(J, I, W);
    k_scores <<<dim3(4,4,NB),   256, SM>>>();
    k_finish <<<2*NBLD/256, 256>>>();
    k_wjwi   <<<dim3(4,4,2*NB), 256, SM>>>();
    k_agg    <<<dim3(16,NB,2),  256, SM>>>(bias);
    k_combine<<<64, 256>>>(out);
}